// round 10
// baseline (speedup 1.0000x reference)
#include <cuda_runtime.h>
#include <math.h>

#define B 4
#define L 1024
#define D 512
#define H 8
#define DK 64
#define DF 2048
#define NL 2
#define HWIN 6
#define SCALE 0.125f
#define NEG -1e9f
#define EPS 1e-5f
#define ROWS (B*L)
#define BH (B*H)

// ---- scratch (device globals; no allocations allowed) ----
__device__ float g_q[B*L*D];
__device__ float g_k[B*L*D];
__device__ float g_v[B*L*D];
__device__ float g_x[B*L*D];
__device__ float g_tmp[B*L*D];
__device__ float g_ao[B*L*D];
__device__ float g_ff[B*L*DF];
__device__ float g_scores[(size_t)BH*L*L];   // masked pre-softmax scores (carried across layers)

// ============================================================
// helpers: raw-bit tf32 (HW truncates), mma, cp.async
// ============================================================
__device__ __forceinline__ void mma8(float* d, const unsigned* a, const unsigned* b) {
    asm volatile("mma.sync.aligned.m16n8k8.row.col.f32.tf32.tf32.f32 "
                 "{%0,%1,%2,%3}, {%4,%5,%6,%7}, {%8,%9}, {%0,%1,%2,%3};\n"
                 : "+f"(d[0]), "+f"(d[1]), "+f"(d[2]), "+f"(d[3])
                 : "r"(a[0]), "r"(a[1]), "r"(a[2]), "r"(a[3]),
                   "r"(b[0]), "r"(b[1]));
}
__device__ __forceinline__ void cpa16(float* s, const float* g) {
    unsigned a = (unsigned)__cvta_generic_to_shared(s);
    asm volatile("cp.async.cg.shared.global [%0], [%1], 16;\n" :: "r"(a), "l"(g));
}
#define CP_COMMIT() asm volatile("cp.async.commit_group;\n" ::: "memory")
#define CP_WAIT0()  asm volatile("cp.async.wait_group 0;\n" ::: "memory")

// dynamic smem: 2 stages, BK=32
//   A stage: 128 rows x 36 floats (32 data + 4 pad) = 4608 floats
//   B stage: 32 rows x 136 floats (128 data + 8 pad) = 4352 floats
#define ASTF 4608
#define BSTF 4352
#define GEMM_SMEM (2*(ASTF+BSTF)*4)   // 71680 bytes

// ============================================================
// GEMM body: C[.,N] tile (bm,bn) = A[.,K] @ W[K,N] + bias, opt GELU.
// 128x128 tile, BK=32, 256 thr (8 warps 4x2, warptile 32x64),
// 2-stage cp.async, single barrier per tile. M%128==0, N%128==0, K%32==0.
// ============================================================
template<int GELU>
__device__ __forceinline__ void gemm_body(const float* __restrict__ A,
                                          const float* __restrict__ W,
                                          const float* __restrict__ bias,
                                          float* __restrict__ C,
                                          int N, int K, int bm, int bn,
                                          float* smA, float* smB) {
    int tid = threadIdx.x;
    int lane = tid & 31, w = tid >> 5;
    int grp = lane >> 2, tg = lane & 3;
    int wm = (w >> 1) * 32, wn = (w & 1) * 64;
    int ar = tid >> 1, aco = (tid & 1) * 16;   // A: 2 threads/row, 16 floats each
    int br = tid >> 3, bco = (tid & 7) * 16;   // B: 8 threads/row, 16 floats each

    float acc[2][8][4];
    #pragma unroll
    for (int i = 0; i < 2; i++)
        #pragma unroll
        for (int j = 0; j < 8; j++)
            #pragma unroll
            for (int c = 0; c < 4; c++) acc[i][j][c] = 0.f;

    const float* Ap = A + (size_t)(bm + ar) * K + aco;
    const float* Wp = W + (size_t)br * N + bn + bco;
    int T = K >> 5;

    auto issue = [&](int t) {
        int s = t & 1;
        const float* a = Ap + (t << 5);
        float* da = &smA[s*ASTF + ar*36 + aco];
        #pragma unroll
        for (int i = 0; i < 4; i++) cpa16(da + i*4, a + i*4);
        const float* bsrc = Wp + (size_t)(t << 5) * N;
        float* db = &smB[s*BSTF + br*136 + bco];
        #pragma unroll
        for (int i = 0; i < 4; i++) cpa16(db + i*4, bsrc + i*4);
    };

    issue(0);
    CP_COMMIT();

    for (int t = 0; t < T; t++) {
        CP_WAIT0();            // own stage-t copies done
        __syncthreads();       // all threads' stage-t done; stage t-1 retired
        if (t + 1 < T) { issue(t + 1); CP_COMMIT(); }
        const float* As = &smA[(t & 1) * ASTF];
        const float* Bs = &smB[(t & 1) * BSTF];
        #pragma unroll
        for (int ks = 0; ks < 32; ks += 8) {
            unsigned af[2][4], bf[8][2];
            #pragma unroll
            for (int mi = 0; mi < 2; mi++) {
                int m = wm + mi * 16 + grp;
                af[mi][0] = __float_as_uint(As[m*36 + ks + tg]);
                af[mi][1] = __float_as_uint(As[(m+8)*36 + ks + tg]);
                af[mi][2] = __float_as_uint(As[m*36 + ks + tg + 4]);
                af[mi][3] = __float_as_uint(As[(m+8)*36 + ks + tg + 4]);
            }
            #pragma unroll
            for (int ni = 0; ni < 8; ni++) {
                int n = wn + ni * 8 + grp;
                bf[ni][0] = __float_as_uint(Bs[(ks+tg)*136 + n]);
                bf[ni][1] = __float_as_uint(Bs[(ks+tg+4)*136 + n]);
            }
            #pragma unroll
            for (int mi = 0; mi < 2; mi++)
                #pragma unroll
                for (int ni = 0; ni < 8; ni++)
                    mma8(acc[mi][ni], af[mi], bf[ni]);
        }
    }

    #pragma unroll
    for (int mi = 0; mi < 2; mi++)
        #pragma unroll
        for (int ni = 0; ni < 8; ni++) {
            int row = bm + wm + mi * 16 + grp;
            int col = bn + wn + ni * 8 + tg * 2;
            float bs0 = bias[col], bs1 = bias[col + 1];
            float v0 = acc[mi][ni][0] + bs0, v1 = acc[mi][ni][1] + bs1;
            float v2 = acc[mi][ni][2] + bs0, v3 = acc[mi][ni][3] + bs1;
            if (GELU) {
                v0 = 0.5f * v0 * (1.0f + erff(v0 * 0.70710678118654752f));
                v1 = 0.5f * v1 * (1.0f + erff(v1 * 0.70710678118654752f));
                v2 = 0.5f * v2 * (1.0f + erff(v2 * 0.70710678118654752f));
                v3 = 0.5f * v3 * (1.0f + erff(v3 * 0.70710678118654752f));
            }
            float2* p0 = (float2*)(C + (size_t)row * N + col);
            float2* p1 = (float2*)(C + (size_t)(row + 8) * N + col);
            *p0 = make_float2(v0, v1);
            *p1 = make_float2(v2, v3);
        }
}

template<int GELU>
__global__ __launch_bounds__(256, 2) void gemm_tf32(const float* __restrict__ A,
                                                    const float* __restrict__ W,
                                                    const float* __restrict__ bias,
                                                    float* __restrict__ C,
                                                    int N, int K) {
    extern __shared__ float dyn[];
    gemm_body<GELU>(A, W, bias, C, N, K, blockIdx.y * 128, blockIdx.x * 128,
                    dyn, dyn + 2*ASTF);
}

// fused QKV: blockIdx.x in [0,12): sel = bx>>2 picks {q,k,v}, (bx&3) n-tile.
__global__ __launch_bounds__(256, 2) void qkv_gemm(const float* __restrict__ A,
        const float* __restrict__ Wq, const float* __restrict__ bq,
        const float* __restrict__ Wk, const float* __restrict__ bk,
        const float* __restrict__ Wv, const float* __restrict__ bv,
        float* __restrict__ q, float* __restrict__ k, float* __restrict__ v) {
    extern __shared__ float dyn[];
    int sel = blockIdx.x >> 2;
    const float* W = sel == 0 ? Wq : (sel == 1 ? Wk : Wv);
    const float* bias = sel == 0 ? bq : (sel == 1 ? bk : bv);
    float* C = sel == 0 ? q : (sel == 1 ? k : v);
    gemm_body<0>(A, W, bias, C, D, D, blockIdx.y * 128, (blockIdx.x & 3) * 128,
                 dyn, dyn + 2*ASTF);
}

// ============================================================
// Fused attention (M=0 softmax shift): per (bh, 128-row i-strip) block:
//   pass1: S = QK^T*SCALE (+prev), mask, write scores
//   pass2: re-read scores (L2-hot), p = exp(s), row-sum, O = P@V, normalize
// ============================================================
__global__ __launch_bounds__(256) void attn_fused(const float* __restrict__ q,
                                                  const float* __restrict__ k,
                                                  const float* __restrict__ v,
                                                  float* __restrict__ scores,
                                                  float* __restrict__ ao,
                                                  int add_prev) {
    __shared__ float s_red[256];
    __shared__ float inv_row[128];
    __shared__ float u[8704];   // pass1: Qs[128][68] then Bs[2][16][136]; pass2: Ps+Vs

    int bh = blockIdx.y;
    int b = bh >> 3, h = bh & 7;
    int i0 = blockIdx.x * 128;
    int tid = threadIdx.x, lane = tid & 31, w = tid >> 5;
    int grp = lane >> 2, tg = lane & 3;
    int wm = (w >> 1) * 32, wn = (w & 1) * 64;

    // ---------------- pass 1 ----------------
    {   // stage Q strip [128][64] -> u (row stride 68)
        const float4* qsrc = (const float4*)(q + ((size_t)b * L + i0) * D + h * DK);
        #pragma unroll
        for (int it = 0; it < 8; it++) {
            int idx = tid + it * 256;
            int row = idx >> 4, c4 = idx & 15;
            float4 t = qsrc[(size_t)row * (D / 4) + c4];
            float* dst = &u[row * 68 + c4 * 4];
            dst[0] = t.x; dst[1] = t.y; dst[2] = t.z; dst[3] = t.w;
        }
    }
    __syncthreads();
    unsigned af[8][2][4];                      // Q fragments live in regs all of pass1
    #pragma unroll
    for (int ks = 0; ks < 8; ks++)
        #pragma unroll
        for (int mi = 0; mi < 2; mi++) {
            int m = wm + mi * 16 + grp;
            af[ks][mi][0] = __float_as_uint(u[m * 68 + ks * 8 + tg]);
            af[ks][mi][1] = __float_as_uint(u[(m + 8) * 68 + ks * 8 + tg]);
            af[ks][mi][2] = __float_as_uint(u[m * 68 + ks * 8 + tg + 4]);
            af[ks][mi][3] = __float_as_uint(u[(m + 8) * 68 + ks * 8 + tg + 4]);
        }
    __syncthreads();

    float (*Bs)[16][136] = (float (*)[16][136])u;
    float acc[2][8][4];
    #pragma unroll
    for (int i = 0; i < 2; i++)
        #pragma unroll
        for (int j = 0; j < 8; j++)
            #pragma unroll
            for (int c = 0; c < 4; c++) acc[i][j][c] = 0.f;

    const float* kbase = k + (size_t)b * L * D + h * DK;
    float* sb = scores + (size_t)bh * L * L;
    int jj = tid >> 1, kc = (tid & 1) * 8;

    {   // prefetch chunk (jt=0,c=0)
        const float* src = kbase + (size_t)jj * D + kc;
        float4 ca = *(const float4*)(src), cb = *(const float4*)(src + 4);
        Bs[0][kc+0][jj]=ca.x; Bs[0][kc+1][jj]=ca.y;
        Bs[0][kc+2][jj]=ca.z; Bs[0][kc+3][jj]=ca.w;
        Bs[0][kc+4][jj]=cb.x; Bs[0][kc+5][jj]=cb.y;
        Bs[0][kc+6][jj]=cb.z; Bs[0][kc+7][jj]=cb.w;
    }
    __syncthreads();

    for (int jt = 0; jt < 8; jt++) {
        #pragma unroll
        for (int c = 0; c < 4; c++) {
            int buf = c & 1;
            int nch = jt * 4 + c + 1;
            float4 na, nb;
            if (nch < 32) {
                const float* src = kbase + (size_t)((nch >> 2) * 128 + jj) * D + (nch & 3) * 16 + kc;
                na = *(const float4*)(src); nb = *(const float4*)(src + 4);
            }
            #pragma unroll
            for (int ksl = 0; ksl < 2; ksl++) {
                unsigned bf[8][2];
                #pragma unroll
                for (int ni = 0; ni < 8; ni++) {
                    int n = wn + ni * 8 + grp;
                    bf[ni][0] = __float_as_uint(Bs[buf][ksl*8 + tg][n]);
                    bf[ni][1] = __float_as_uint(Bs[buf][ksl*8 + tg + 4][n]);
                }
                #pragma unroll
                for (int mi = 0; mi < 2; mi++)
                    #pragma unroll
                    for (int ni = 0; ni < 8; ni++)
                        mma8(acc[mi][ni], af[c*2 + ksl][mi], bf[ni]);
            }
            if (c == 3) {   // j-tile epilogue
                #pragma unroll
                for (int mi = 0; mi < 2; mi++)
                    #pragma unroll
                    for (int ni = 0; ni < 8; ni++) {
                        int gi = i0 + wm + mi * 16 + grp;
                        int gj = jt * 128 + wn + ni * 8 + tg * 2;
                        #pragma unroll
                        for (int rr = 0; rr < 2; rr++) {
                            int row = gi + rr * 8;
                            float s0 = acc[mi][ni][rr*2 + 0] * SCALE;
                            float s1 = acc[mi][ni][rr*2 + 1] * SCALE;
                            float2* p = (float2*)(sb + (size_t)row * L + gj);
                            if (add_prev) { float2 pv = *p; s0 += pv.x; s1 += pv.y; }
                            int d0 = row - gj;     d0 = d0 < 0 ? -d0 : d0;
                            int d1 = row - gj - 1; d1 = d1 < 0 ? -d1 : d1;
                            if (d0 < HWIN) s0 = NEG;
                            if (d1 < HWIN) s1 = NEG;
                            *p = make_float2(s0, s1);
                            acc[mi][ni][rr*2 + 0] = 0.f;
                            acc[mi][ni][rr*2 + 1] = 0.f;
                        }
                    }
            }
            if (nch < 32) {
                int nb2 = buf ^ 1;
                Bs[nb2][kc+0][jj]=na.x; Bs[nb2][kc+1][jj]=na.y;
                Bs[nb2][kc+2][jj]=na.z; Bs[nb2][kc+3][jj]=na.w;
                Bs[nb2][kc+4][jj]=nb.x; Bs[nb2][kc+5][jj]=nb.y;
                Bs[nb2][kc+6][jj]=nb.z; Bs[nb2][kc+7][jj]=nb.w;
            }
            __syncthreads();
        }
    }

    // ---------------- pass 2: O = softmax(S) @ V  (exp(s), M=0) ----------------
    int ar = tid >> 1, ac = (tid & 1) * 8;
    int br = tid >> 4, bc = (tid & 15) * 4;
    int wn2 = (w & 1) * 32;
    float (*Ps)[128][20] = (float (*)[128][20])u;
    float (*Vs)[16][72]  = (float (*)[16][72])(u + 5120);
    const float* Sp = sb + (size_t)(i0 + ar) * L + ac;
    const float* Vp = v + (size_t)b * L * D + h * DK + (size_t)br * D + bc;
    float sum_part = 0.f;
    float acc2[2][4][4];
    #pragma unroll
    for (int i = 0; i < 2; i++)
        #pragma unroll
        for (int j = 0; j < 4; j++)
            #pragma unroll
            for (int c = 0; c < 4; c++) acc2[i][j][c] = 0.f;

    {   // stage chunk 0
        float4 s0 = *(const float4*)(Sp), s1 = *(const float4*)(Sp + 4);
        float4 vv = *(const float4*)(Vp);
        float p0=__expf(s0.x), p1=__expf(s0.y), p2=__expf(s0.z), p3=__expf(s0.w);
        float p4=__expf(s1.x), p5=__expf(s1.y), p6=__expf(s1.z), p7=__expf(s1.w);
        sum_part += p0+p1+p2+p3+p4+p5+p6+p7;
        float* pd = &Ps[0][ar][ac];
        pd[0]=p0; pd[1]=p1; pd[2]=p2; pd[3]=p3;
        pd[4]=p4; pd[5]=p5; pd[6]=p6; pd[7]=p7;
        Vs[0][br][bc+0]=vv.x; Vs[0][br][bc+1]=vv.y;
        Vs[0][br][bc+2]=vv.z; Vs[0][br][bc+3]=vv.w;
    }
    __syncthreads();

    for (int t = 0; t < 64; t++) {
        int buf = t & 1;
        float4 ns0, ns1, nv;
        if (t + 1 < 64) {
            ns0 = *(const float4*)(Sp + (t+1)*16);
            ns1 = *(const float4*)(Sp + (t+1)*16 + 4);
            nv  = *(const float4*)(Vp + (size_t)(t+1) * 16 * D);
        }
        #pragma unroll
        for (int ksl = 0; ksl < 2; ksl++) {
            unsigned a2[2][4], b2[4][2];
            #pragma unroll
            for (int mi = 0; mi < 2; mi++) {
                int m = wm + mi * 16 + grp;
                a2[mi][0] = __float_as_uint(Ps[buf][m][ksl*8 + tg]);
                a2[mi][1] = __float_as_uint(Ps[buf][m + 8][ksl*8 + tg]);
                a2[mi][2] = __float_as_uint(Ps[buf][m][ksl*8 + tg + 4]);
                a2[mi][3] = __float_as_uint(Ps[buf][m + 8][ksl*8 + tg + 4]);
            }
            #pragma unroll
            for (int ni = 0; ni < 4; ni++) {
                int n = wn2 + ni * 8 + grp;
                b2[ni][0] = __float_as_uint(Vs[buf][ksl*8 + tg][n]);
                b2[ni][1] = __float_as_uint(Vs[buf][ksl*8 + tg + 4][n]);
            }
            #pragma unroll
            for (int mi = 0; mi < 2; mi++)
                #pragma unroll
                for (int ni = 0; ni < 4; ni++)
                    mma8(acc2[mi][ni], a2[mi], b2[ni]);
        }
        if (t + 1 < 64) {
            int nb2 = buf ^ 1;
            float p0=__expf(ns0.x), p1=__expf(ns0.y), p2=__expf(ns0.z), p3=__expf(ns0.w);
            float p4=__expf(ns1.x), p5=__expf(ns1.y), p6=__expf(ns1.z), p7=__expf(ns1.w);
            sum_part += p0+p1+p2+p3+p4+p5+p6+p7;
            float* pd = &Ps[nb2][ar][ac];
            pd[0]=p0; pd[1]=p1; pd[2]=p2; pd[3]=p3;
            pd[4]=p4; pd[5]=p5; pd[6]=p6; pd[7]=p7;
            Vs[nb2][br][bc+0]=nv.x; Vs[nb2][br][bc+1]=nv.y;
            Vs[nb2][br][bc+2]=nv.z; Vs[nb2][br][bc+3]=nv.w;
        }
        __syncthreads();
    }

    s_red[tid] = sum_part;
    __syncthreads();
    if (tid < 128) inv_row[tid] = 1.0f / (s_red[2*tid] + s_red[2*tid + 1]);
    __syncthreads();

    float* ob = ao + (size_t)b * L * D + h * DK;
    #pragma unroll
    for (int mi = 0; mi < 2; mi++)
        #pragma unroll
        for (int ni = 0; ni < 4; ni++) {
            int rl = wm + mi * 16 + grp;
            int col = wn2 + ni * 8 + tg * 2;
            float iv0 = inv_row[rl], iv1 = inv_row[rl + 8];
            float2* p0 = (float2*)(ob + (size_t)(i0 + rl) * D + col);
            float2* p1 = (float2*)(ob + (size_t)(i0 + rl + 8) * D + col);
            *p0 = make_float2(acc2[mi][ni][0] * iv0, acc2[mi][ni][1] * iv0);
            *p1 = make_float2(acc2[mi][ni][2] * iv1, acc2[mi][ni][3] * iv1);
        }
}

// ============================================================
// out = LayerNorm(x + r) * gamma + beta. One block (128 thr) per row of 512.
// ============================================================
__global__ void addln_kernel(const float* __restrict__ x, const float* __restrict__ r,
                             const float* __restrict__ gam, const float* __restrict__ bet,
                             float* __restrict__ out) {
    int row = blockIdx.x;
    int tid = threadIdx.x;
    const float4* xp = (const float4*)(x + (size_t)row * D);
    const float4* rp = (const float4*)(r + (size_t)row * D);
    float4 a = xp[tid], b4 = rp[tid];
    float e0 = a.x + b4.x, e1 = a.y + b4.y, e2 = a.z + b4.z, e3 = a.w + b4.w;
    float s = e0 + e1 + e2 + e3;
    float qq = e0*e0 + e1*e1 + e2*e2 + e3*e3;
    __shared__ float rs[4], rq[4];
    #pragma unroll
    for (int off = 16; off; off >>= 1) {
        s  += __shfl_xor_sync(0xffffffffu, s, off);
        qq += __shfl_xor_sync(0xffffffffu, qq, off);
    }
    if ((tid & 31) == 0) { rs[tid >> 5] = s; rq[tid >> 5] = qq; }
    __syncthreads();
    s  = rs[0] + rs[1] + rs[2] + rs[3];
    qq = rq[0] + rq[1] + rq[2] + rq[3];
    float mean = s * (1.0f / D);
    float var  = qq * (1.0f / D) - mean * mean;
    float inv  = rsqrtf(var + EPS);
    float4 g4 = ((const float4*)gam)[tid];
    float4 bb = ((const float4*)bet)[tid];
    float4 ov;
    ov.x = (e0 - mean) * inv * g4.x + bb.x;
    ov.y = (e1 - mean) * inv * g4.y + bb.y;
    ov.z = (e2 - mean) * inv * g4.z + bb.z;
    ov.w = (e3 - mean) * inv * g4.w + bb.w;
    ((float4*)(out + (size_t)row * D))[tid] = ov;
}

// ============================================================
extern "C" void kernel_launch(void* const* d_in, const int* in_sizes, int n_in,
                              void* d_out, int out_size) {
    const float* src = (const float*)d_in[0];
    const float* Wq = (const float*)d_in[1];  const float* bq = (const float*)d_in[2];
    const float* Wk = (const float*)d_in[3];  const float* bk = (const float*)d_in[4];
    const float* Wv = (const float*)d_in[5];  const float* bv = (const float*)d_in[6];
    const float* Wo = (const float*)d_in[7];  const float* bo = (const float*)d_in[8];
    const float* W1 = (const float*)d_in[9];  const float* b1 = (const float*)d_in[10];
    const float* W2 = (const float*)d_in[11]; const float* b2 = (const float*)d_in[12];
    const float* ln1g = (const float*)d_in[13]; const float* ln1b = (const float*)d_in[14];
    const float* ln2g = (const float*)d_in[15]; const float* ln2b = (const float*)d_in[16];

    float *q, *k, *v, *x, *tmp, *ao, *ff, *sc;
    cudaGetSymbolAddress((void**)&q,  g_q);
    cudaGetSymbolAddress((void**)&k,  g_k);
    cudaGetSymbolAddress((void**)&v,  g_v);
    cudaGetSymbolAddress((void**)&x,  g_x);
    cudaGetSymbolAddress((void**)&tmp, g_tmp);
    cudaGetSymbolAddress((void**)&ao, g_ao);
    cudaGetSymbolAddress((void**)&ff, g_ff);
    cudaGetSymbolAddress((void**)&sc, g_scores);

    cudaFuncSetAttribute(gemm_tf32<0>, cudaFuncAttributeMaxDynamicSharedMemorySize, GEMM_SMEM);
    cudaFuncSetAttribute(gemm_tf32<1>, cudaFuncAttributeMaxDynamicSharedMemorySize, GEMM_SMEM);
    cudaFuncSetAttribute(qkv_gemm,     cudaFuncAttributeMaxDynamicSharedMemorySize, GEMM_SMEM);

    dim3 gD(D/128, ROWS/128);     // 4 x 32
    dim3 gDF(DF/128, ROWS/128);   // 16 x 32
    dim3 gQKV(12, ROWS/128);      // 12 x 32
    dim3 gA(L/128, BH);           // 8 x 32

    const float* xin = src;
    for (int l = 0; l < NL; l++) {
        qkv_gemm<<<gQKV, 256, GEMM_SMEM>>>(xin,
            Wq + (size_t)l*D*D, bq + (size_t)l*D,
            Wk + (size_t)l*D*D, bk + (size_t)l*D,
            Wv + (size_t)l*D*D, bv + (size_t)l*D, q, k, v);
        attn_fused<<<gA, 256>>>(q, k, v, sc, ao, l > 0 ? 1 : 0);
        gemm_tf32<0><<<gD, 256, GEMM_SMEM>>>(ao, Wo + (size_t)l*D*D, bo + (size_t)l*D, tmp, D, D);
        addln_kernel<<<ROWS, 128>>>(xin, tmp, ln1g + (size_t)l*D, ln1b + (size_t)l*D, x);
        gemm_tf32<1><<<gDF, 256, GEMM_SMEM>>>(x, W1 + (size_t)l*D*DF, b1 + (size_t)l*DF, ff, DF, D);
        gemm_tf32<0><<<gD, 256, GEMM_SMEM>>>(ff, W2 + (size_t)l*DF*D, b2 + (size_t)l*D, tmp, D, DF);
        float* lnout = (l == NL-1) ? (float*)d_out : x;
        addln_kernel<<<ROWS, 128>>>(x, tmp, ln2g + (size_t)l*D, ln2b + (size_t)l*D, lnout);
        xin = x;
    }
}

// round 11
// speedup vs baseline: 1.1317x; 1.1317x over previous
#include <cuda_runtime.h>
#include <math.h>

#define B 4
#define L 1024
#define D 512
#define H 8
#define DK 64
#define DF 2048
#define NL 2
#define HWIN 6
#define SCALE 0.125f
#define NEG -1e9f
#define EPS 1e-5f
#define ROWS (B*L)
#define BH (B*H)

// ---- scratch (device globals; no allocations allowed) ----
__device__ float g_q[B*L*D];
__device__ float g_k[B*L*D];
__device__ float g_v[B*L*D];
__device__ float g_x[B*L*D];
__device__ float g_tmp[B*L*D];
__device__ float g_ao[B*L*D];
__device__ float g_ff[B*L*DF];
__device__ float g_scores[(size_t)BH*L*L];   // masked pre-softmax scores (carried across layers)

// ============================================================
// helpers: raw-bit tf32 (HW truncates), mma, cp.async
// ============================================================
__device__ __forceinline__ void mma8(float* d, const unsigned* a, const unsigned* b) {
    asm volatile("mma.sync.aligned.m16n8k8.row.col.f32.tf32.tf32.f32 "
                 "{%0,%1,%2,%3}, {%4,%5,%6,%7}, {%8,%9}, {%0,%1,%2,%3};\n"
                 : "+f"(d[0]), "+f"(d[1]), "+f"(d[2]), "+f"(d[3])
                 : "r"(a[0]), "r"(a[1]), "r"(a[2]), "r"(a[3]),
                   "r"(b[0]), "r"(b[1]));
}
__device__ __forceinline__ void cpa16(float* s, const float* g) {
    unsigned a = (unsigned)__cvta_generic_to_shared(s);
    asm volatile("cp.async.cg.shared.global [%0], [%1], 16;\n" :: "r"(a), "l"(g));
}
#define CP_COMMIT() asm volatile("cp.async.commit_group;\n" ::: "memory")
#define CP_WAIT1()  asm volatile("cp.async.wait_group 1;\n" ::: "memory")

// dynamic smem layout for GEMM: 3 stages (R7 config)
//   A stage: 128 rows x stride 20 floats = 2560 floats
//   B stage: 16 rows x stride 136 floats = 2176 floats
#define AST 2560
#define BST 2176
#define GEMM_SMEM (3*(AST+BST)*4)   // 56832 bytes

// ============================================================
// GEMM body: C[.,N] tile (bm,bn) = A[.,K] @ W[K,N] + bias, opt GELU.
// 128x128 tile, BK=16, 256 thr (8 warps 4x2, warptile 32x64),
// cp.async 3-stage pipeline, raw-bit tf32 mma. M%128==0, N%128==0, K%16==0.
// ============================================================
template<int GELU>
__device__ __forceinline__ void gemm_body(const float* __restrict__ A,
                                          const float* __restrict__ W,
                                          const float* __restrict__ bias,
                                          float* __restrict__ C,
                                          int N, int K, int bm, int bn,
                                          float* smA, float* smB) {
    int tid = threadIdx.x;
    int lane = tid & 31, w = tid >> 5;
    int grp = lane >> 2, tg = lane & 3;
    int wm = (w >> 1) * 32, wn = (w & 1) * 64;
    int ar = tid >> 1, ac = (tid & 1) * 8;
    int br = tid >> 4, bc = (tid & 15) * 8;

    float acc[2][8][4];
    #pragma unroll
    for (int i = 0; i < 2; i++)
        #pragma unroll
        for (int j = 0; j < 8; j++)
            #pragma unroll
            for (int c = 0; c < 4; c++) acc[i][j][c] = 0.f;

    const float* Ap = A + (size_t)(bm + ar) * K + ac;
    const float* Wp = W + (size_t)br * N + bn + bc;
    int T = K >> 4;

    auto issue = [&](int t) {
        int s = t % 3;
        const float* a = Ap + (t << 4);
        cpa16(&smA[s*AST + ar*20 + ac],     a);
        cpa16(&smA[s*AST + ar*20 + ac + 4], a + 4);
        const float* bsrc = Wp + (size_t)(t << 4) * N;
        cpa16(&smB[s*BST + br*136 + bc],     bsrc);
        cpa16(&smB[s*BST + br*136 + bc + 4], bsrc + 4);
    };

    if (0 < T) issue(0);
    CP_COMMIT();
    if (1 < T) issue(1);
    CP_COMMIT();

    for (int t = 0; t < T; t++) {
        CP_WAIT1();
        __syncthreads();
        if (t + 2 < T) issue(t + 2);
        CP_COMMIT();
        const float* As = &smA[(t % 3) * AST];
        const float* Bs = &smB[(t % 3) * BST];
        #pragma unroll
        for (int ks = 0; ks < 16; ks += 8) {
            unsigned af[2][4], bf[8][2];
            #pragma unroll
            for (int mi = 0; mi < 2; mi++) {
                int m = wm + mi * 16 + grp;
                af[mi][0] = __float_as_uint(As[m*20 + ks + tg]);
                af[mi][1] = __float_as_uint(As[(m+8)*20 + ks + tg]);
                af[mi][2] = __float_as_uint(As[m*20 + ks + tg + 4]);
                af[mi][3] = __float_as_uint(As[(m+8)*20 + ks + tg + 4]);
            }
            #pragma unroll
            for (int ni = 0; ni < 8; ni++) {
                int n = wn + ni * 8 + grp;
                bf[ni][0] = __float_as_uint(Bs[(ks+tg)*136 + n]);
                bf[ni][1] = __float_as_uint(Bs[(ks+tg+4)*136 + n]);
            }
            #pragma unroll
            for (int mi = 0; mi < 2; mi++)
                #pragma unroll
                for (int ni = 0; ni < 8; ni++)
                    mma8(acc[mi][ni], af[mi], bf[ni]);
        }
        __syncthreads();
    }

    #pragma unroll
    for (int mi = 0; mi < 2; mi++)
        #pragma unroll
        for (int ni = 0; ni < 8; ni++) {
            int row = bm + wm + mi * 16 + grp;
            int col = bn + wn + ni * 8 + tg * 2;
            float bs0 = bias[col], bs1 = bias[col + 1];
            float v0 = acc[mi][ni][0] + bs0, v1 = acc[mi][ni][1] + bs1;
            float v2 = acc[mi][ni][2] + bs0, v3 = acc[mi][ni][3] + bs1;
            if (GELU) {
                v0 = 0.5f * v0 * (1.0f + erff(v0 * 0.70710678118654752f));
                v1 = 0.5f * v1 * (1.0f + erff(v1 * 0.70710678118654752f));
                v2 = 0.5f * v2 * (1.0f + erff(v2 * 0.70710678118654752f));
                v3 = 0.5f * v3 * (1.0f + erff(v3 * 0.70710678118654752f));
            }
            float2* p0 = (float2*)(C + (size_t)row * N + col);
            float2* p1 = (float2*)(C + (size_t)(row + 8) * N + col);
            *p0 = make_float2(v0, v1);
            *p1 = make_float2(v2, v3);
        }
}

template<int GELU>
__global__ __launch_bounds__(256, 2) void gemm_tf32(const float* __restrict__ A,
                                                    const float* __restrict__ W,
                                                    const float* __restrict__ bias,
                                                    float* __restrict__ C,
                                                    int N, int K) {
    extern __shared__ float dyn[];
    gemm_body<GELU>(A, W, bias, C, N, K, blockIdx.y * 128, blockIdx.x * 128,
                    dyn, dyn + 3*AST);
}

// fused QKV: blockIdx.x in [0,12): sel = bx>>2 picks {q,k,v}, (bx&3) n-tile.
__global__ __launch_bounds__(256, 2) void qkv_gemm(const float* __restrict__ A,
        const float* __restrict__ Wq, const float* __restrict__ bq,
        const float* __restrict__ Wk, const float* __restrict__ bk,
        const float* __restrict__ Wv, const float* __restrict__ bv,
        float* __restrict__ q, float* __restrict__ k, float* __restrict__ v) {
    extern __shared__ float dyn[];
    int sel = blockIdx.x >> 2;
    const float* W = sel == 0 ? Wq : (sel == 1 ? Wk : Wv);
    const float* bias = sel == 0 ? bq : (sel == 1 ? bk : bv);
    float* C = sel == 0 ? q : (sel == 1 ? k : v);
    gemm_body<0>(A, W, bias, C, D, D, blockIdx.y * 128, (blockIdx.x & 3) * 128,
                 dyn, dyn + 3*AST);
}

// ============================================================
// Fused attention (M=0 softmax): per (bh, 128-row i-strip) block:
//   pass1: S = QK^T*SCALE (+prev), mask, write scores
//   pass2: re-read scores (L2-hot), p = exp(s), row-sum, O = P@V, normalize
// pass2 uses BK=32 chunks (32 barriers instead of 64). Dynamic smem.
//   Ps[2][128][36] = 9216 floats, Vs[2][32][72] = 4608 floats -> 13824 floats
// ============================================================
#define ATT_SMEM (13824*4)   // 55296 bytes

__global__ __launch_bounds__(256) void attn_fused(const float* __restrict__ q,
                                                  const float* __restrict__ k,
                                                  const float* __restrict__ v,
                                                  float* __restrict__ scores,
                                                  float* __restrict__ ao,
                                                  int add_prev) {
    __shared__ float s_red[256];
    __shared__ float inv_row[128];
    extern __shared__ float u[];

    int bh = blockIdx.y;
    int b = bh >> 3, h = bh & 7;
    int i0 = blockIdx.x * 128;
    int tid = threadIdx.x, lane = tid & 31, w = tid >> 5;
    int grp = lane >> 2, tg = lane & 3;
    int wm = (w >> 1) * 32, wn = (w & 1) * 64;

    // ---------------- pass 1 ----------------
    {   // stage Q strip [128][64] -> u (row stride 68)
        const float4* qsrc = (const float4*)(q + ((size_t)b * L + i0) * D + h * DK);
        #pragma unroll
        for (int it = 0; it < 8; it++) {
            int idx = tid + it * 256;
            int row = idx >> 4, c4 = idx & 15;
            float4 t = qsrc[(size_t)row * (D / 4) + c4];
            float* dst = &u[row * 68 + c4 * 4];
            dst[0] = t.x; dst[1] = t.y; dst[2] = t.z; dst[3] = t.w;
        }
    }
    __syncthreads();
    unsigned af[8][2][4];                      // Q fragments live in regs all of pass1
    #pragma unroll
    for (int ks = 0; ks < 8; ks++)
        #pragma unroll
        for (int mi = 0; mi < 2; mi++) {
            int m = wm + mi * 16 + grp;
            af[ks][mi][0] = __float_as_uint(u[m * 68 + ks * 8 + tg]);
            af[ks][mi][1] = __float_as_uint(u[(m + 8) * 68 + ks * 8 + tg]);
            af[ks][mi][2] = __float_as_uint(u[m * 68 + ks * 8 + tg + 4]);
            af[ks][mi][3] = __float_as_uint(u[(m + 8) * 68 + ks * 8 + tg + 4]);
        }
    __syncthreads();

    float (*Bs)[16][136] = (float (*)[16][136])u;
    float acc[2][8][4];
    #pragma unroll
    for (int i = 0; i < 2; i++)
        #pragma unroll
        for (int j = 0; j < 8; j++)
            #pragma unroll
            for (int c = 0; c < 4; c++) acc[i][j][c] = 0.f;

    const float* kbase = k + (size_t)b * L * D + h * DK;
    float* sb = scores + (size_t)bh * L * L;
    int jj = tid >> 1, kc = (tid & 1) * 8;

    {   // prefetch chunk (jt=0,c=0)
        const float* src = kbase + (size_t)jj * D + kc;
        float4 ca = *(const float4*)(src), cb = *(const float4*)(src + 4);
        Bs[0][kc+0][jj]=ca.x; Bs[0][kc+1][jj]=ca.y;
        Bs[0][kc+2][jj]=ca.z; Bs[0][kc+3][jj]=ca.w;
        Bs[0][kc+4][jj]=cb.x; Bs[0][kc+5][jj]=cb.y;
        Bs[0][kc+6][jj]=cb.z; Bs[0][kc+7][jj]=cb.w;
    }
    __syncthreads();

    for (int jt = 0; jt < 8; jt++) {
        #pragma unroll
        for (int c = 0; c < 4; c++) {
            int buf = c & 1;
            int nch = jt * 4 + c + 1;
            float4 na, nb;
            if (nch < 32) {
                const float* src = kbase + (size_t)((nch >> 2) * 128 + jj) * D + (nch & 3) * 16 + kc;
                na = *(const float4*)(src); nb = *(const float4*)(src + 4);
            }
            #pragma unroll
            for (int ksl = 0; ksl < 2; ksl++) {
                unsigned bf[8][2];
                #pragma unroll
                for (int ni = 0; ni < 8; ni++) {
                    int n = wn + ni * 8 + grp;
                    bf[ni][0] = __float_as_uint(Bs[buf][ksl*8 + tg][n]);
                    bf[ni][1] = __float_as_uint(Bs[buf][ksl*8 + tg + 4][n]);
                }
                #pragma unroll
                for (int mi = 0; mi < 2; mi++)
                    #pragma unroll
                    for (int ni = 0; ni < 8; ni++)
                        mma8(acc[mi][ni], af[c*2 + ksl][mi], bf[ni]);
            }
            if (c == 3) {   // j-tile epilogue
                #pragma unroll
                for (int mi = 0; mi < 2; mi++)
                    #pragma unroll
                    for (int ni = 0; ni < 8; ni++) {
                        int gi = i0 + wm + mi * 16 + grp;
                        int gj = jt * 128 + wn + ni * 8 + tg * 2;
                        #pragma unroll
                        for (int rr = 0; rr < 2; rr++) {
                            int row = gi + rr * 8;
                            float s0 = acc[mi][ni][rr*2 + 0] * SCALE;
                            float s1 = acc[mi][ni][rr*2 + 1] * SCALE;
                            float2* p = (float2*)(sb + (size_t)row * L + gj);
                            if (add_prev) { float2 pv = *p; s0 += pv.x; s1 += pv.y; }
                            int d0 = row - gj;     d0 = d0 < 0 ? -d0 : d0;
                            int d1 = row - gj - 1; d1 = d1 < 0 ? -d1 : d1;
                            if (d0 < HWIN) s0 = NEG;
                            if (d1 < HWIN) s1 = NEG;
                            *p = make_float2(s0, s1);
                            acc[mi][ni][rr*2 + 0] = 0.f;
                            acc[mi][ni][rr*2 + 1] = 0.f;
                        }
                    }
            }
            if (nch < 32) {
                int nb2 = buf ^ 1;
                Bs[nb2][kc+0][jj]=na.x; Bs[nb2][kc+1][jj]=na.y;
                Bs[nb2][kc+2][jj]=na.z; Bs[nb2][kc+3][jj]=na.w;
                Bs[nb2][kc+4][jj]=nb.x; Bs[nb2][kc+5][jj]=nb.y;
                Bs[nb2][kc+6][jj]=nb.z; Bs[nb2][kc+7][jj]=nb.w;
            }
            __syncthreads();
        }
    }

    // ---------------- pass 2: O = softmax(S) @ V, BK=32 chunks ----------------
    int ar = tid >> 1, ac = (tid & 1) * 16;    // S: 2 thr/row, 16 floats each
    int br = tid >> 3, bc = (tid & 7) * 8;     // V: 8 thr/row, 8 floats each
    int wn2 = (w & 1) * 32;
    float (*Ps)[128][36] = (float (*)[128][36])u;
    float (*Vs)[32][72]  = (float (*)[32][72])(u + 9216);
    const float* Sp = sb + (size_t)(i0 + ar) * L + ac;
    const float* Vp = v + (size_t)b * L * D + h * DK + (size_t)br * D + bc;
    float sum_part = 0.f;
    float acc2[2][4][4];
    #pragma unroll
    for (int i = 0; i < 2; i++)
        #pragma unroll
        for (int j = 0; j < 4; j++)
            #pragma unroll
            for (int c = 0; c < 4; c++) acc2[i][j][c] = 0.f;

    {   // stage chunk 0
        #pragma unroll
        for (int i = 0; i < 4; i++) {
            float4 sv = *(const float4*)(Sp + i*4);
            float p0=__expf(sv.x), p1=__expf(sv.y), p2=__expf(sv.z), p3=__expf(sv.w);
            sum_part += p0+p1+p2+p3;
            float* pd = &Ps[0][ar][ac + i*4];
            pd[0]=p0; pd[1]=p1; pd[2]=p2; pd[3]=p3;
        }
        float4 v0 = *(const float4*)(Vp), v1 = *(const float4*)(Vp + 4);
        float* vd = &Vs[0][br][bc];
        vd[0]=v0.x; vd[1]=v0.y; vd[2]=v0.z; vd[3]=v0.w;
        vd[4]=v1.x; vd[5]=v1.y; vd[6]=v1.z; vd[7]=v1.w;
    }
    __syncthreads();

    for (int t = 0; t < 32; t++) {
        int buf = t & 1;
        float4 ns[4], nv0, nv1;
        if (t + 1 < 32) {
            #pragma unroll
            for (int i = 0; i < 4; i++)
                ns[i] = *(const float4*)(Sp + (t+1)*32 + i*4);
            nv0 = *(const float4*)(Vp + (size_t)(t+1) * 32 * D);
            nv1 = *(const float4*)(Vp + (size_t)(t+1) * 32 * D + 4);
        }
        #pragma unroll
        for (int ksl = 0; ksl < 4; ksl++) {
            unsigned a2[2][4], b2[4][2];
            #pragma unroll
            for (int mi = 0; mi < 2; mi++) {
                int m = wm + mi * 16 + grp;
                a2[mi][0] = __float_as_uint(Ps[buf][m][ksl*8 + tg]);
                a2[mi][1] = __float_as_uint(Ps[buf][m + 8][ksl*8 + tg]);
                a2[mi][2] = __float_as_uint(Ps[buf][m][ksl*8 + tg + 4]);
                a2[mi][3] = __float_as_uint(Ps[buf][m + 8][ksl*8 + tg + 4]);
            }
            #pragma unroll
            for (int ni = 0; ni < 4; ni++) {
                int n = wn2 + ni * 8 + grp;
                b2[ni][0] = __float_as_uint(Vs[buf][ksl*8 + tg][n]);
                b2[ni][1] = __float_as_uint(Vs[buf][ksl*8 + tg + 4][n]);
            }
            #pragma unroll
            for (int mi = 0; mi < 2; mi++)
                #pragma unroll
                for (int ni = 0; ni < 4; ni++)
                    mma8(acc2[mi][ni], a2[mi], b2[ni]);
        }
        if (t + 1 < 32) {
            int nb2 = buf ^ 1;
            #pragma unroll
            for (int i = 0; i < 4; i++) {
                float p0=__expf(ns[i].x), p1=__expf(ns[i].y),
                      p2=__expf(ns[i].z), p3=__expf(ns[i].w);
                sum_part += p0+p1+p2+p3;
                float* pd = &Ps[nb2][ar][ac + i*4];
                pd[0]=p0; pd[1]=p1; pd[2]=p2; pd[3]=p3;
            }
            float* vd = &Vs[nb2][br][bc];
            vd[0]=nv0.x; vd[1]=nv0.y; vd[2]=nv0.z; vd[3]=nv0.w;
            vd[4]=nv1.x; vd[5]=nv1.y; vd[6]=nv1.z; vd[7]=nv1.w;
        }
        __syncthreads();
    }

    s_red[tid] = sum_part;
    __syncthreads();
    if (tid < 128) inv_row[tid] = 1.0f / (s_red[2*tid] + s_red[2*tid + 1]);
    __syncthreads();

    float* ob = ao + (size_t)b * L * D + h * DK;
    #pragma unroll
    for (int mi = 0; mi < 2; mi++)
        #pragma unroll
        for (int ni = 0; ni < 4; ni++) {
            int rl = wm + mi * 16 + grp;
            int col = wn2 + ni * 8 + tg * 2;
            float iv0 = inv_row[rl], iv1 = inv_row[rl + 8];
            float2* p0 = (float2*)(ob + (size_t)(i0 + rl) * D + col);
            float2* p1 = (float2*)(ob + (size_t)(i0 + rl + 8) * D + col);
            *p0 = make_float2(acc2[mi][ni][0] * iv0, acc2[mi][ni][1] * iv0);
            *p1 = make_float2(acc2[mi][ni][2] * iv1, acc2[mi][ni][3] * iv1);
        }
}

// ============================================================
// out = LayerNorm(x + r) * gamma + beta. One block (128 thr) per row of 512.
// ============================================================
__global__ void addln_kernel(const float* __restrict__ x, const float* __restrict__ r,
                             const float* __restrict__ gam, const float* __restrict__ bet,
                             float* __restrict__ out) {
    int row = blockIdx.x;
    int tid = threadIdx.x;
    const float4* xp = (const float4*)(x + (size_t)row * D);
    const float4* rp = (const float4*)(r + (size_t)row * D);
    float4 a = xp[tid], b4 = rp[tid];
    float e0 = a.x + b4.x, e1 = a.y + b4.y, e2 = a.z + b4.z, e3 = a.w + b4.w;
    float s = e0 + e1 + e2 + e3;
    float qq = e0*e0 + e1*e1 + e2*e2 + e3*e3;
    __shared__ float rs[4], rq[4];
    #pragma unroll
    for (int off = 16; off; off >>= 1) {
        s  += __shfl_xor_sync(0xffffffffu, s, off);
        qq += __shfl_xor_sync(0xffffffffu, qq, off);
    }
    if ((tid & 31) == 0) { rs[tid >> 5] = s; rq[tid >> 5] = qq; }
    __syncthreads();
    s  = rs[0] + rs[1] + rs[2] + rs[3];
    qq = rq[0] + rq[1] + rq[2] + rq[3];
    float mean = s * (1.0f / D);
    float var  = qq * (1.0f / D) - mean * mean;
    float inv  = rsqrtf(var + EPS);
    float4 g4 = ((const float4*)gam)[tid];
    float4 bb = ((const float4*)bet)[tid];
    float4 ov;
    ov.x = (e0 - mean) * inv * g4.x + bb.x;
    ov.y = (e1 - mean) * inv * g4.y + bb.y;
    ov.z = (e2 - mean) * inv * g4.z + bb.z;
    ov.w = (e3 - mean) * inv * g4.w + bb.w;
    ((float4*)(out + (size_t)row * D))[tid] = ov;
}

// ============================================================
extern "C" void kernel_launch(void* const* d_in, const int* in_sizes, int n_in,
                              void* d_out, int out_size) {
    const float* src = (const float*)d_in[0];
    const float* Wq = (const float*)d_in[1];  const float* bq = (const float*)d_in[2];
    const float* Wk = (const float*)d_in[3];  const float* bk = (const float*)d_in[4];
    const float* Wv = (const float*)d_in[5];  const float* bv = (const float*)d_in[6];
    const float* Wo = (const float*)d_in[7];  const float* bo = (const float*)d_in[8];
    const float* W1 = (const float*)d_in[9];  const float* b1 = (const float*)d_in[10];
    const float* W2 = (const float*)d_in[11]; const float* b2 = (const float*)d_in[12];
    const float* ln1g = (const float*)d_in[13]; const float* ln1b = (const float*)d_in[14];
    const float* ln2g = (const float*)d_in[15]; const float* ln2b = (const float*)d_in[16];

    float *q, *k, *v, *x, *tmp, *ao, *ff, *sc;
    cudaGetSymbolAddress((void**)&q,  g_q);
    cudaGetSymbolAddress((void**)&k,  g_k);
    cudaGetSymbolAddress((void**)&v,  g_v);
    cudaGetSymbolAddress((void**)&x,  g_x);
    cudaGetSymbolAddress((void**)&tmp, g_tmp);
    cudaGetSymbolAddress((void**)&ao, g_ao);
    cudaGetSymbolAddress((void**)&ff, g_ff);
    cudaGetSymbolAddress((void**)&sc, g_scores);

    cudaFuncSetAttribute(gemm_tf32<0>, cudaFuncAttributeMaxDynamicSharedMemorySize, GEMM_SMEM);
    cudaFuncSetAttribute(gemm_tf32<1>, cudaFuncAttributeMaxDynamicSharedMemorySize, GEMM_SMEM);
    cudaFuncSetAttribute(qkv_gemm,     cudaFuncAttributeMaxDynamicSharedMemorySize, GEMM_SMEM);
    cudaFuncSetAttribute(attn_fused,   cudaFuncAttributeMaxDynamicSharedMemorySize, ATT_SMEM);

    dim3 gD(D/128, ROWS/128);     // 4 x 32
    dim3 gDF(DF/128, ROWS/128);   // 16 x 32
    dim3 gQKV(12, ROWS/128);      // 12 x 32
    dim3 gA(L/128, BH);           // 8 x 32

    const float* xin = src;
    for (int l = 0; l < NL; l++) {
        qkv_gemm<<<gQKV, 256, GEMM_SMEM>>>(xin,
            Wq + (size_t)l*D*D, bq + (size_t)l*D,
            Wk + (size_t)l*D*D, bk + (size_t)l*D,
            Wv + (size_t)l*D*D, bv + (size_t)l*D, q, k, v);
        attn_fused<<<gA, 256, ATT_SMEM>>>(q, k, v, sc, ao, l > 0 ? 1 : 0);
        gemm_tf32<0><<<gD, 256, GEMM_SMEM>>>(ao, Wo + (size_t)l*D*D, bo + (size_t)l*D, tmp, D, D);
        addln_kernel<<<ROWS, 128>>>(xin, tmp, ln1g + (size_t)l*D, ln1b + (size_t)l*D, x);
        gemm_tf32<1><<<gDF, 256, GEMM_SMEM>>>(x, W1 + (size_t)l*D*DF, b1 + (size_t)l*DF, ff, DF, D);
        gemm_tf32<0><<<gD, 256, GEMM_SMEM>>>(ff, W2 + (size_t)l*DF*D, b2 + (size_t)l*D, tmp, D, DF);
        float* lnout = (l == NL-1) ? (float*)d_out : x;
        addln_kernel<<<ROWS, 128>>>(x, tmp, ln2g + (size_t)l*D, ln2b + (size_t)l*D, lnout);
        xin = x;
    }
}

// round 13
// speedup vs baseline: 1.1711x; 1.0349x over previous
#include <cuda_runtime.h>
#include <math.h>

#define B 4
#define L 1024
#define D 512
#define H 8
#define DK 64
#define DF 2048
#define NL 2
#define HWIN 6
#define SCALE 0.125f
#define NEG -1e9f
#define EPS 1e-5f
#define ROWS (B*L)
#define BH (B*H)

// ---- scratch (device globals; no allocations allowed) ----
__device__ float g_q[B*L*D];
__device__ float g_k[B*L*D];
__device__ float g_v[B*L*D];
__device__ float g_x[B*L*D];
__device__ float g_tmp[B*L*D];
__device__ float g_ao[B*L*D];
__device__ float g_ff[B*L*DF];
__device__ float g_scores[(size_t)BH*L*L];   // masked pre-softmax scores (carried across layers)

// ============================================================
// helpers: raw-bit tf32 (HW truncates), mma, cp.async
// ============================================================
__device__ __forceinline__ void mma8(float* d, const unsigned* a, const unsigned* b) {
    asm volatile("mma.sync.aligned.m16n8k8.row.col.f32.tf32.tf32.f32 "
                 "{%0,%1,%2,%3}, {%4,%5,%6,%7}, {%8,%9}, {%0,%1,%2,%3};\n"
                 : "+f"(d[0]), "+f"(d[1]), "+f"(d[2]), "+f"(d[3])
                 : "r"(a[0]), "r"(a[1]), "r"(a[2]), "r"(a[3]),
                   "r"(b[0]), "r"(b[1]));
}
__device__ __forceinline__ void cpa16(float* s, const float* g) {
    unsigned a = (unsigned)__cvta_generic_to_shared(s);
    asm volatile("cp.async.cg.shared.global [%0], [%1], 16;\n" :: "r"(a), "l"(g));
}
#define CP_COMMIT() asm volatile("cp.async.commit_group;\n" ::: "memory")
#define CP_WAIT0()  asm volatile("cp.async.wait_group 0;\n" ::: "memory")
#define CP_WAIT1()  asm volatile("cp.async.wait_group 1;\n" ::: "memory")

// dynamic smem layout for GEMM: 3 stages (R7/R11 config)
#define AST 2560
#define BST 2176
#define GEMM_SMEM (3*(AST+BST)*4)   // 56832 bytes

// ============================================================
// GEMM body: unchanged from R11 (validated fastest mma.sync config).
// ============================================================
template<int GELU>
__device__ __forceinline__ void gemm_body(const float* __restrict__ A,
                                          const float* __restrict__ W,
                                          const float* __restrict__ bias,
                                          float* __restrict__ C,
                                          int N, int K, int bm, int bn,
                                          float* smA, float* smB) {
    int tid = threadIdx.x;
    int lane = tid & 31, w = tid >> 5;
    int grp = lane >> 2, tg = lane & 3;
    int wm = (w >> 1) * 32, wn = (w & 1) * 64;
    int ar = tid >> 1, ac = (tid & 1) * 8;
    int br = tid >> 4, bc = (tid & 15) * 8;

    float acc[2][8][4];
    #pragma unroll
    for (int i = 0; i < 2; i++)
        #pragma unroll
        for (int j = 0; j < 8; j++)
            #pragma unroll
            for (int c = 0; c < 4; c++) acc[i][j][c] = 0.f;

    const float* Ap = A + (size_t)(bm + ar) * K + ac;
    const float* Wp = W + (size_t)br * N + bn + bc;
    int T = K >> 4;

    auto issue = [&](int t) {
        int s = t % 3;
        const float* a = Ap + (t << 4);
        cpa16(&smA[s*AST + ar*20 + ac],     a);
        cpa16(&smA[s*AST + ar*20 + ac + 4], a + 4);
        const float* bsrc = Wp + (size_t)(t << 4) * N;
        cpa16(&smB[s*BST + br*136 + bc],     bsrc);
        cpa16(&smB[s*BST + br*136 + bc + 4], bsrc + 4);
    };

    if (0 < T) issue(0);
    CP_COMMIT();
    if (1 < T) issue(1);
    CP_COMMIT();

    for (int t = 0; t < T; t++) {
        CP_WAIT1();
        __syncthreads();
        if (t + 2 < T) issue(t + 2);
        CP_COMMIT();
        const float* As = &smA[(t % 3) * AST];
        const float* Bs = &smB[(t % 3) * BST];
        #pragma unroll
        for (int ks = 0; ks < 16; ks += 8) {
            unsigned af[2][4], bf[8][2];
            #pragma unroll
            for (int mi = 0; mi < 2; mi++) {
                int m = wm + mi * 16 + grp;
                af[mi][0] = __float_as_uint(As[m*20 + ks + tg]);
                af[mi][1] = __float_as_uint(As[(m+8)*20 + ks + tg]);
                af[mi][2] = __float_as_uint(As[m*20 + ks + tg + 4]);
                af[mi][3] = __float_as_uint(As[(m+8)*20 + ks + tg + 4]);
            }
            #pragma unroll
            for (int ni = 0; ni < 8; ni++) {
                int n = wn + ni * 8 + grp;
                bf[ni][0] = __float_as_uint(Bs[(ks+tg)*136 + n]);
                bf[ni][1] = __float_as_uint(Bs[(ks+tg+4)*136 + n]);
            }
            #pragma unroll
            for (int mi = 0; mi < 2; mi++)
                #pragma unroll
                for (int ni = 0; ni < 8; ni++)
                    mma8(acc[mi][ni], af[mi], bf[ni]);
        }
        __syncthreads();
    }

    #pragma unroll
    for (int mi = 0; mi < 2; mi++)
        #pragma unroll
        for (int ni = 0; ni < 8; ni++) {
            int row = bm + wm + mi * 16 + grp;
            int col = bn + wn + ni * 8 + tg * 2;
            float bs0 = bias[col], bs1 = bias[col + 1];
            float v0 = acc[mi][ni][0] + bs0, v1 = acc[mi][ni][1] + bs1;
            float v2 = acc[mi][ni][2] + bs0, v3 = acc[mi][ni][3] + bs1;
            if (GELU) {
                v0 = 0.5f * v0 * (1.0f + erff(v0 * 0.70710678118654752f));
                v1 = 0.5f * v1 * (1.0f + erff(v1 * 0.70710678118654752f));
                v2 = 0.5f * v2 * (1.0f + erff(v2 * 0.70710678118654752f));
                v3 = 0.5f * v3 * (1.0f + erff(v3 * 0.70710678118654752f));
            }
            float2* p0 = (float2*)(C + (size_t)row * N + col);
            float2* p1 = (float2*)(C + (size_t)(row + 8) * N + col);
            *p0 = make_float2(v0, v1);
            *p1 = make_float2(v2, v3);
        }
}

template<int GELU>
__global__ __launch_bounds__(256, 2) void gemm_tf32(const float* __restrict__ A,
                                                    const float* __restrict__ W,
                                                    const float* __restrict__ bias,
                                                    float* __restrict__ C,
                                                    int N, int K) {
    extern __shared__ float dyn[];
    gemm_body<GELU>(A, W, bias, C, N, K, blockIdx.y * 128, blockIdx.x * 128,
                    dyn, dyn + 3*AST);
}

// fused QKV: blockIdx.x in [0,12): sel = bx>>2 picks {q,k,v}, (bx&3) n-tile.
__global__ __launch_bounds__(256, 2) void qkv_gemm(const float* __restrict__ A,
        const float* __restrict__ Wq, const float* __restrict__ bq,
        const float* __restrict__ Wk, const float* __restrict__ bk,
        const float* __restrict__ Wv, const float* __restrict__ bv,
        float* __restrict__ q, float* __restrict__ k, float* __restrict__ v) {
    extern __shared__ float dyn[];
    int sel = blockIdx.x >> 2;
    const float* W = sel == 0 ? Wq : (sel == 1 ? Wk : Wv);
    const float* bias = sel == 0 ? bq : (sel == 1 ? bk : bv);
    float* C = sel == 0 ? q : (sel == 1 ? k : v);
    gemm_body<0>(A, W, bias, C, D, D, blockIdx.y * 128, (blockIdx.x & 3) * 128,
                 dyn, dyn + 3*AST);
}

// ============================================================
// Single-pass fused attention (M=0 softmax, streaming PV):
// per (bh, 128-row i-strip) block, for each of 8 j-tiles:
//   QK^T mma -> s (scale, +prev, mask) -> write scores (residual carry)
//   p = exp(s) -> smem exchange -> P@V mma accumulated across j-tiles
// Row sums accumulate per-thread; final normalize at the end.
// smem (floats): Qs[128][68]=8704 | Bs[2][16][136]=4352 |
//                Ps[128][132]=16896 | Vs[128][72]=9216   -> 39168
// ============================================================
#define ATT_QS 0
#define ATT_BS 8704
#define ATT_PS 13056
#define ATT_VS 29952
#define ATT_SMEM (39168*4)   // 156672 bytes

__global__ __launch_bounds__(256) void attn_fused(const float* __restrict__ q,
                                                  const float* __restrict__ k,
                                                  const float* __restrict__ v,
                                                  float* __restrict__ scores,
                                                  float* __restrict__ ao,
                                                  int add_prev) {
    __shared__ float m_part[2][128];
    __shared__ float inv_row[128];
    extern __shared__ float u[];
    float* Qs = u + ATT_QS;                                   // [128][68]
    float (*Bs)[16][136] = (float (*)[16][136])(u + ATT_BS);  // [2][16][136]
    float* Ps = u + ATT_PS;                                   // [128][132]
    float* Vs = u + ATT_VS;                                   // [128][72]

    int bh = blockIdx.y;
    int b = bh >> 3, h = bh & 7;
    int i0 = blockIdx.x * 128;
    int tid = threadIdx.x, lane = tid & 31, w = tid >> 5;
    int grp = lane >> 2, tg = lane & 3;
    int wm = (w >> 1) * 32, wn = (w & 1) * 64, wn2 = (w & 1) * 32;

    // stage Q strip [128][64] -> Qs (row stride 68)
    {
        const float4* qsrc = (const float4*)(q + ((size_t)b * L + i0) * D + h * DK);
        #pragma unroll
        for (int it = 0; it < 8; it++) {
            int idx = tid + it * 256;
            int row = idx >> 4, c4 = idx & 15;
            float4 t = qsrc[(size_t)row * (D / 4) + c4];
            float* dst = &Qs[row * 68 + c4 * 4];
            dst[0] = t.x; dst[1] = t.y; dst[2] = t.z; dst[3] = t.w;
        }
    }

    float acc[2][8][4];
    float acc2[2][4][4];
    float sum_acc[4] = {0.f, 0.f, 0.f, 0.f};
    #pragma unroll
    for (int i = 0; i < 2; i++) {
        #pragma unroll
        for (int j = 0; j < 8; j++)
            #pragma unroll
            for (int c = 0; c < 4; c++) acc[i][j][c] = 0.f;
        #pragma unroll
        for (int j = 0; j < 4; j++)
            #pragma unroll
            for (int c = 0; c < 4; c++) acc2[i][j][c] = 0.f;
    }

    const float* kbase = k + (size_t)b * L * D + h * DK;
    const float* vbase = v + (size_t)b * L * D + h * DK;
    float* sb = scores + (size_t)bh * L * L;
    int jj = tid >> 1, kc = (tid & 1) * 8;
    int vr = tid >> 1, vc = (tid & 1) * 32;

    auto issueV = [&](int jt) {
        const float* src = vbase + (size_t)(jt * 128 + vr) * D + vc;
        float* dst = &Vs[vr * 72 + vc];
        #pragma unroll
        for (int i = 0; i < 8; i++) cpa16(dst + i * 4, src + i * 4);
        CP_COMMIT();
    };

    {   // prefetch K chunk 0 -> Bs[0]
        const float* src = kbase + (size_t)jj * D + kc;
        float4 ca = *(const float4*)(src), cb = *(const float4*)(src + 4);
        Bs[0][kc+0][jj]=ca.x; Bs[0][kc+1][jj]=ca.y;
        Bs[0][kc+2][jj]=ca.z; Bs[0][kc+3][jj]=ca.w;
        Bs[0][kc+4][jj]=cb.x; Bs[0][kc+5][jj]=cb.y;
        Bs[0][kc+6][jj]=cb.z; Bs[0][kc+7][jj]=cb.w;
    }
    issueV(0);
    __syncthreads();

    for (int jt = 0; jt < 8; jt++) {
        // ---- QK^T over 4 chunks of 16 k each ----
        #pragma unroll
        for (int c = 0; c < 4; c++) {
            int buf = c & 1;
            int nch = jt * 4 + c + 1;
            float4 na, nb;
            if (nch < 32) {
                const float* src = kbase + (size_t)((nch >> 2) * 128 + jj) * D + (nch & 3) * 16 + kc;
                na = *(const float4*)(src); nb = *(const float4*)(src + 4);
            }
            #pragma unroll
            for (int ksl = 0; ksl < 2; ksl++) {
                int kk = c * 16 + ksl * 8;
                unsigned af[2][4], bf[8][2];
                #pragma unroll
                for (int mi = 0; mi < 2; mi++) {
                    int m = wm + mi * 16 + grp;
                    af[mi][0] = __float_as_uint(Qs[m * 68 + kk + tg]);
                    af[mi][1] = __float_as_uint(Qs[(m + 8) * 68 + kk + tg]);
                    af[mi][2] = __float_as_uint(Qs[m * 68 + kk + tg + 4]);
                    af[mi][3] = __float_as_uint(Qs[(m + 8) * 68 + kk + tg + 4]);
                }
                #pragma unroll
                for (int ni = 0; ni < 8; ni++) {
                    int n = wn + ni * 8 + grp;
                    bf[ni][0] = __float_as_uint(Bs[buf][ksl*8 + tg][n]);
                    bf[ni][1] = __float_as_uint(Bs[buf][ksl*8 + tg + 4][n]);
                }
                #pragma unroll
                for (int mi = 0; mi < 2; mi++)
                    #pragma unroll
                    for (int ni = 0; ni < 8; ni++)
                        mma8(acc[mi][ni], af[mi], bf[ni]);
            }
            if (c == 3) {   // epilogue: s -> scores(global) + p -> Ps(smem)
                #pragma unroll
                for (int mi = 0; mi < 2; mi++)
                    #pragma unroll
                    for (int ni = 0; ni < 8; ni++) {
                        int rl = wm + mi * 16 + grp;
                        int cl = wn + ni * 8 + tg * 2;
                        int gj = jt * 128 + cl;
                        #pragma unroll
                        for (int rr = 0; rr < 2; rr++) {
                            int row = i0 + rl + rr * 8;
                            float s0 = acc[mi][ni][rr*2 + 0] * SCALE;
                            float s1 = acc[mi][ni][rr*2 + 1] * SCALE;
                            float2* p = (float2*)(sb + (size_t)row * L + gj);
                            if (add_prev) { float2 pv = *p; s0 += pv.x; s1 += pv.y; }
                            int d0 = row - gj;     d0 = d0 < 0 ? -d0 : d0;
                            int d1 = row - gj - 1; d1 = d1 < 0 ? -d1 : d1;
                            if (d0 < HWIN) s0 = NEG;
                            if (d1 < HWIN) s1 = NEG;
                            *p = make_float2(s0, s1);
                            float p0 = __expf(s0), p1 = __expf(s1);
                            sum_acc[mi*2 + rr] += p0 + p1;
                            float2* pp = (float2*)&Ps[(rl + rr*8) * 132 + cl];
                            *pp = make_float2(p0, p1);
                            acc[mi][ni][rr*2 + 0] = 0.f;
                            acc[mi][ni][rr*2 + 1] = 0.f;
                        }
                    }
            }
            if (nch < 32) {
                int nb2 = buf ^ 1;
                Bs[nb2][kc+0][jj]=na.x; Bs[nb2][kc+1][jj]=na.y;
                Bs[nb2][kc+2][jj]=na.z; Bs[nb2][kc+3][jj]=na.w;
                Bs[nb2][kc+4][jj]=nb.x; Bs[nb2][kc+5][jj]=nb.y;
                Bs[nb2][kc+6][jj]=nb.z; Bs[nb2][kc+7][jj]=nb.w;
            }
            __syncthreads();
        }

        // ---- PV for this j-tile: acc2 += P(128x128) @ V(128x64) ----
        CP_WAIT0();          // own V copies done
        __syncthreads();     // everyone's V copies visible
        #pragma unroll
        for (int ksl = 0; ksl < 16; ksl++) {
            unsigned a2[2][4], b2[4][2];
            #pragma unroll
            for (int mi = 0; mi < 2; mi++) {
                int m = wm + mi * 16 + grp;
                a2[mi][0] = __float_as_uint(Ps[m * 132 + ksl*8 + tg]);
                a2[mi][1] = __float_as_uint(Ps[(m + 8) * 132 + ksl*8 + tg]);
                a2[mi][2] = __float_as_uint(Ps[m * 132 + ksl*8 + tg + 4]);
                a2[mi][3] = __float_as_uint(Ps[(m + 8) * 132 + ksl*8 + tg + 4]);
            }
            #pragma unroll
            for (int ni = 0; ni < 4; ni++) {
                int n = wn2 + ni * 8 + grp;
                b2[ni][0] = __float_as_uint(Vs[(ksl*8 + tg) * 72 + n]);
                b2[ni][1] = __float_as_uint(Vs[(ksl*8 + tg + 4) * 72 + n]);
            }
            #pragma unroll
            for (int mi = 0; mi < 2; mi++)
                #pragma unroll
                for (int ni = 0; ni < 4; ni++)
                    mma8(acc2[mi][ni], a2[mi], b2[ni]);
        }
        __syncthreads();     // Ps/Vs safe to overwrite
        if (jt + 1 < 8) issueV(jt + 1);
    }

    // ---- row-sum reduction ----
    #pragma unroll
    for (int mi = 0; mi < 2; mi++)
        #pragma unroll
        for (int rr = 0; rr < 2; rr++) {
            float s = sum_acc[mi*2 + rr];
            s += __shfl_xor_sync(0xffffffffu, s, 1);
            s += __shfl_xor_sync(0xffffffffu, s, 2);
            if (tg == 0) m_part[w & 1][wm + mi*16 + grp + rr*8] = s;
        }
    __syncthreads();
    if (tid < 128) inv_row[tid] = 1.0f / (m_part[0][tid] + m_part[1][tid]);
    __syncthreads();

    float* ob = ao + (size_t)b * L * D + h * DK;
    #pragma unroll
    for (int mi = 0; mi < 2; mi++)
        #pragma unroll
        for (int ni = 0; ni < 4; ni++) {
            int rl = wm + mi * 16 + grp;
            int col = wn2 + ni * 8 + tg * 2;
            float iv0 = inv_row[rl], iv1 = inv_row[rl + 8];
            float2* p0 = (float2*)(ob + (size_t)(i0 + rl) * D + col);
            float2* p1 = (float2*)(ob + (size_t)(i0 + rl + 8) * D + col);
            *p0 = make_float2(acc2[mi][ni][0] * iv0, acc2[mi][ni][1] * iv0);
            *p1 = make_float2(acc2[mi][ni][2] * iv1, acc2[mi][ni][3] * iv1);
        }
}

// ============================================================
// out = LayerNorm(x + r) * gamma + beta. One block (128 thr) per row of 512.
// ============================================================
__global__ void addln_kernel(const float* __restrict__ x, const float* __restrict__ r,
                             const float* __restrict__ gam, const float* __restrict__ bet,
                             float* __restrict__ out) {
    int row = blockIdx.x;
    int tid = threadIdx.x;
    const float4* xp = (const float4*)(x + (size_t)row * D);
    const float4* rp = (const float4*)(r + (size_t)row * D);
    float4 a = xp[tid], b4 = rp[tid];
    float e0 = a.x + b4.x, e1 = a.y + b4.y, e2 = a.z + b4.z, e3 = a.w + b4.w;
    float s = e0 + e1 + e2 + e3;
    float qq = e0*e0 + e1*e1 + e2*e2 + e3*e3;
    __shared__ float rs[4], rq[4];
    #pragma unroll
    for (int off = 16; off; off >>= 1) {
        s  += __shfl_xor_sync(0xffffffffu, s, off);
        qq += __shfl_xor_sync(0xffffffffu, qq, off);
    }
    if ((tid & 31) == 0) { rs[tid >> 5] = s; rq[tid >> 5] = qq; }
    __syncthreads();
    s  = rs[0] + rs[1] + rs[2] + rs[3];
    qq = rq[0] + rq[1] + rq[2] + rq[3];
    float mean = s * (1.0f / D);
    float var  = qq * (1.0f / D) - mean * mean;
    float inv  = rsqrtf(var + EPS);
    float4 g4 = ((const float4*)gam)[tid];
    float4 bb = ((const float4*)bet)[tid];
    float4 ov;
    ov.x = (e0 - mean) * inv * g4.x + bb.x;
    ov.y = (e1 - mean) * inv * g4.y + bb.y;
    ov.z = (e2 - mean) * inv * g4.z + bb.z;
    ov.w = (e3 - mean) * inv * g4.w + bb.w;
    ((float4*)(out + (size_t)row * D))[tid] = ov;
}

// ============================================================
extern "C" void kernel_launch(void* const* d_in, const int* in_sizes, int n_in,
                              void* d_out, int out_size) {
    const float* src = (const float*)d_in[0];
    const float* Wq = (const float*)d_in[1];  const float* bq = (const float*)d_in[2];
    const float* Wk = (const float*)d_in[3];  const float* bk = (const float*)d_in[4];
    const float* Wv = (const float*)d_in[5];  const float* bv = (const float*)d_in[6];
    const float* Wo = (const float*)d_in[7];  const float* bo = (const float*)d_in[8];
    const float* W1 = (const float*)d_in[9];  const float* b1 = (const float*)d_in[10];
    const float* W2 = (const float*)d_in[11]; const float* b2 = (const float*)d_in[12];
    const float* ln1g = (const float*)d_in[13]; const float* ln1b = (const float*)d_in[14];
    const float* ln2g = (const float*)d_in[15]; const float* ln2b = (const float*)d_in[16];

    float *q, *k, *v, *x, *tmp, *ao, *ff, *sc;
    cudaGetSymbolAddress((void**)&q,  g_q);
    cudaGetSymbolAddress((void**)&k,  g_k);
    cudaGetSymbolAddress((void**)&v,  g_v);
    cudaGetSymbolAddress((void**)&x,  g_x);
    cudaGetSymbolAddress((void**)&tmp, g_tmp);
    cudaGetSymbolAddress((void**)&ao, g_ao);
    cudaGetSymbolAddress((void**)&ff, g_ff);
    cudaGetSymbolAddress((void**)&sc, g_scores);

    cudaFuncSetAttribute(gemm_tf32<0>, cudaFuncAttributeMaxDynamicSharedMemorySize, GEMM_SMEM);
    cudaFuncSetAttribute(gemm_tf32<1>, cudaFuncAttributeMaxDynamicSharedMemorySize, GEMM_SMEM);
    cudaFuncSetAttribute(qkv_gemm,     cudaFuncAttributeMaxDynamicSharedMemorySize, GEMM_SMEM);
    cudaFuncSetAttribute(attn_fused,   cudaFuncAttributeMaxDynamicSharedMemorySize, ATT_SMEM);

    dim3 gD(D/128, ROWS/128);     // 4 x 32
    dim3 gDF(DF/128, ROWS/128);   // 16 x 32
    dim3 gQKV(12, ROWS/128);      // 12 x 32
    dim3 gA(L/128, BH);           // 8 x 32

    const float* xin = src;
    for (int l = 0; l < NL; l++) {
        qkv_gemm<<<gQKV, 256, GEMM_SMEM>>>(xin,
            Wq + (size_t)l*D*D, bq + (size_t)l*D,
            Wk + (size_t)l*D*D, bk + (size_t)l*D,
            Wv + (size_t)l*D*D, bv + (size_t)l*D, q, k, v);
        attn_fused<<<gA, 256, ATT_SMEM>>>(q, k, v, sc, ao, l > 0 ? 1 : 0);
        gemm_tf32<0><<<gD, 256, GEMM_SMEM>>>(ao, Wo + (size_t)l*D*D, bo + (size_t)l*D, tmp, D, D);
        addln_kernel<<<ROWS, 128>>>(xin, tmp, ln1g + (size_t)l*D, ln1b + (size_t)l*D, x);
        gemm_tf32<1><<<gDF, 256, GEMM_SMEM>>>(x, W1 + (size_t)l*D*DF, b1 + (size_t)l*DF, ff, DF, D);
        gemm_tf32<0><<<gD, 256, GEMM_SMEM>>>(ff, W2 + (size_t)l*DF*D, b2 + (size_t)l*D, tmp, D, DF);
        float* lnout = (l == NL-1) ? (float*)d_out : x;
        addln_kernel<<<ROWS, 128>>>(x, tmp, ln2g + (size_t)l*D, ln2b + (size_t)l*D, lnout);
        xin = x;
    }
}

// round 14
// speedup vs baseline: 1.1862x; 1.0129x over previous
#include <cuda_runtime.h>
#include <math.h>

#define B 4
#define L 1024
#define D 512
#define H 8
#define DK 64
#define DF 2048
#define NL 2
#define HWIN 6
#define SCALE 0.125f
#define NEG -1e9f
#define EPS 1e-5f
#define ROWS (B*L)
#define BH (B*H)

// ---- scratch (device globals; no allocations allowed) ----
__device__ float g_q[B*L*D];
__device__ float g_k[B*L*D];
__device__ float g_v[B*L*D];
__device__ float g_x[B*L*D];
__device__ float g_tmp[B*L*D];
__device__ float g_ao[B*L*D];
__device__ float g_ff[B*L*DF];
__device__ float g_scores[(size_t)BH*L*L];   // masked pre-softmax scores (carried across layers)

// ============================================================
// helpers: raw-bit tf32 (HW truncates), mma, cp.async
// ============================================================
__device__ __forceinline__ void mma8(float* d, const unsigned* a, const unsigned* b) {
    asm volatile("mma.sync.aligned.m16n8k8.row.col.f32.tf32.tf32.f32 "
                 "{%0,%1,%2,%3}, {%4,%5,%6,%7}, {%8,%9}, {%0,%1,%2,%3};\n"
                 : "+f"(d[0]), "+f"(d[1]), "+f"(d[2]), "+f"(d[3])
                 : "r"(a[0]), "r"(a[1]), "r"(a[2]), "r"(a[3]),
                   "r"(b[0]), "r"(b[1]));
}
__device__ __forceinline__ void cpa16(float* s, const float* g) {
    unsigned a = (unsigned)__cvta_generic_to_shared(s);
    asm volatile("cp.async.cg.shared.global [%0], [%1], 16;\n" :: "r"(a), "l"(g));
}
#define CP_COMMIT() asm volatile("cp.async.commit_group;\n" ::: "memory")
#define CP_WAIT0()  asm volatile("cp.async.wait_group 0;\n" ::: "memory")
#define CP_WAIT1()  asm volatile("cp.async.wait_group 1;\n" ::: "memory")

// dynamic smem layout for GEMM: 3 stages (R7/R11 config)
#define AST 2560
#define BST 2176
#define GEMM_SMEM (3*(AST+BST)*4)   // 56832 bytes

// ============================================================
// GEMM body: R11 config, single barrier per K-tile (trailing sync removed —
// top barrier of iter t already retires compute(t-1) for all threads, and
// issue(t+2) which overwrites stage (t-1)%3 comes after it).
// ============================================================
template<int GELU>
__device__ __forceinline__ void gemm_body(const float* __restrict__ A,
                                          const float* __restrict__ W,
                                          const float* __restrict__ bias,
                                          float* __restrict__ C,
                                          int N, int K, int bm, int bn,
                                          float* smA, float* smB) {
    int tid = threadIdx.x;
    int lane = tid & 31, w = tid >> 5;
    int grp = lane >> 2, tg = lane & 3;
    int wm = (w >> 1) * 32, wn = (w & 1) * 64;
    int ar = tid >> 1, ac = (tid & 1) * 8;
    int br = tid >> 4, bc = (tid & 15) * 8;

    float acc[2][8][4];
    #pragma unroll
    for (int i = 0; i < 2; i++)
        #pragma unroll
        for (int j = 0; j < 8; j++)
            #pragma unroll
            for (int c = 0; c < 4; c++) acc[i][j][c] = 0.f;

    const float* Ap = A + (size_t)(bm + ar) * K + ac;
    const float* Wp = W + (size_t)br * N + bn + bc;
    int T = K >> 4;

    auto issue = [&](int t) {
        int s = t % 3;
        const float* a = Ap + (t << 4);
        cpa16(&smA[s*AST + ar*20 + ac],     a);
        cpa16(&smA[s*AST + ar*20 + ac + 4], a + 4);
        const float* bsrc = Wp + (size_t)(t << 4) * N;
        cpa16(&smB[s*BST + br*136 + bc],     bsrc);
        cpa16(&smB[s*BST + br*136 + bc + 4], bsrc + 4);
    };

    if (0 < T) issue(0);
    CP_COMMIT();
    if (1 < T) issue(1);
    CP_COMMIT();

    for (int t = 0; t < T; t++) {
        CP_WAIT1();
        __syncthreads();
        if (t + 2 < T) issue(t + 2);
        CP_COMMIT();
        const float* As = &smA[(t % 3) * AST];
        const float* Bs = &smB[(t % 3) * BST];
        #pragma unroll
        for (int ks = 0; ks < 16; ks += 8) {
            unsigned af[2][4], bf[8][2];
            #pragma unroll
            for (int mi = 0; mi < 2; mi++) {
                int m = wm + mi * 16 + grp;
                af[mi][0] = __float_as_uint(As[m*20 + ks + tg]);
                af[mi][1] = __float_as_uint(As[(m+8)*20 + ks + tg]);
                af[mi][2] = __float_as_uint(As[m*20 + ks + tg + 4]);
                af[mi][3] = __float_as_uint(As[(m+8)*20 + ks + tg + 4]);
            }
            #pragma unroll
            for (int ni = 0; ni < 8; ni++) {
                int n = wn + ni * 8 + grp;
                bf[ni][0] = __float_as_uint(Bs[(ks+tg)*136 + n]);
                bf[ni][1] = __float_as_uint(Bs[(ks+tg+4)*136 + n]);
            }
            #pragma unroll
            for (int mi = 0; mi < 2; mi++)
                #pragma unroll
                for (int ni = 0; ni < 8; ni++)
                    mma8(acc[mi][ni], af[mi], bf[ni]);
        }
    }

    #pragma unroll
    for (int mi = 0; mi < 2; mi++)
        #pragma unroll
        for (int ni = 0; ni < 8; ni++) {
            int row = bm + wm + mi * 16 + grp;
            int col = bn + wn + ni * 8 + tg * 2;
            float bs0 = bias[col], bs1 = bias[col + 1];
            float v0 = acc[mi][ni][0] + bs0, v1 = acc[mi][ni][1] + bs1;
            float v2 = acc[mi][ni][2] + bs0, v3 = acc[mi][ni][3] + bs1;
            if (GELU) {
                v0 = 0.5f * v0 * (1.0f + erff(v0 * 0.70710678118654752f));
                v1 = 0.5f * v1 * (1.0f + erff(v1 * 0.70710678118654752f));
                v2 = 0.5f * v2 * (1.0f + erff(v2 * 0.70710678118654752f));
                v3 = 0.5f * v3 * (1.0f + erff(v3 * 0.70710678118654752f));
            }
            float2* p0 = (float2*)(C + (size_t)row * N + col);
            float2* p1 = (float2*)(C + (size_t)(row + 8) * N + col);
            *p0 = make_float2(v0, v1);
            *p1 = make_float2(v2, v3);
        }
}

template<int GELU>
__global__ __launch_bounds__(256, 2) void gemm_tf32(const float* __restrict__ A,
                                                    const float* __restrict__ W,
                                                    const float* __restrict__ bias,
                                                    float* __restrict__ C,
                                                    int N, int K) {
    extern __shared__ float dyn[];
    gemm_body<GELU>(A, W, bias, C, N, K, blockIdx.y * 128, blockIdx.x * 128,
                    dyn, dyn + 3*AST);
}

// fused QKV: blockIdx.x in [0,12): sel = bx>>2 picks {q,k,v}, (bx&3) n-tile.
__global__ __launch_bounds__(256, 2) void qkv_gemm(const float* __restrict__ A,
        const float* __restrict__ Wq, const float* __restrict__ bq,
        const float* __restrict__ Wk, const float* __restrict__ bk,
        const float* __restrict__ Wv, const float* __restrict__ bv,
        float* __restrict__ q, float* __restrict__ k, float* __restrict__ v) {
    extern __shared__ float dyn[];
    int sel = blockIdx.x >> 2;
    const float* W = sel == 0 ? Wq : (sel == 1 ? Wk : Wv);
    const float* bias = sel == 0 ? bq : (sel == 1 ? bk : bv);
    float* C = sel == 0 ? q : (sel == 1 ? k : v);
    gemm_body<0>(A, W, bias, C, D, D, blockIdx.y * 128, (blockIdx.x & 3) * 128,
                 dyn, dyn + 3*AST);
}

// ============================================================
// Single-pass fused attention (M=0 softmax, streaming PV, double-buffered V):
// per (bh, 128-row i-strip) block, for each of 8 j-tiles:
//   QK^T mma -> s (scale, +prev, mask) -> write scores (residual carry)
//   p = exp(s) -> smem exchange -> P@V mma accumulated across j-tiles
// V(jt+1) cp.async issued at the START of PV(jt) into the other buffer
// (no post-PV barrier needed).
// smem (floats): Qs[128][68]=8704 | Bs[2][16][136]=4352 |
//                Ps[128][132]=16896 | Vs[2][128][72]=18432 -> 48384
// ============================================================
#define ATT_QS 0
#define ATT_BS 8704
#define ATT_PS 13056
#define ATT_VS 29952
#define ATT_VSTRIDE 9216
#define ATT_SMEM (48384*4)   // 193536 bytes

__global__ __launch_bounds__(256) void attn_fused(const float* __restrict__ q,
                                                  const float* __restrict__ k,
                                                  const float* __restrict__ v,
                                                  float* __restrict__ scores,
                                                  float* __restrict__ ao,
                                                  int add_prev) {
    __shared__ float m_part[2][128];
    __shared__ float inv_row[128];
    extern __shared__ float u[];
    float* Qs = u + ATT_QS;                                   // [128][68]
    float (*Bs)[16][136] = (float (*)[16][136])(u + ATT_BS);  // [2][16][136]
    float* Ps = u + ATT_PS;                                   // [128][132]

    int bh = blockIdx.y;
    int b = bh >> 3, h = bh & 7;
    int i0 = blockIdx.x * 128;
    int tid = threadIdx.x, lane = tid & 31, w = tid >> 5;
    int grp = lane >> 2, tg = lane & 3;
    int wm = (w >> 1) * 32, wn = (w & 1) * 64, wn2 = (w & 1) * 32;

    // stage Q strip [128][64] -> Qs (row stride 68)
    {
        const float4* qsrc = (const float4*)(q + ((size_t)b * L + i0) * D + h * DK);
        #pragma unroll
        for (int it = 0; it < 8; it++) {
            int idx = tid + it * 256;
            int row = idx >> 4, c4 = idx & 15;
            float4 t = qsrc[(size_t)row * (D / 4) + c4];
            float* dst = &Qs[row * 68 + c4 * 4];
            dst[0] = t.x; dst[1] = t.y; dst[2] = t.z; dst[3] = t.w;
        }
    }

    float acc[2][8][4];
    float acc2[2][4][4];
    float sum_acc[4] = {0.f, 0.f, 0.f, 0.f};
    #pragma unroll
    for (int i = 0; i < 2; i++) {
        #pragma unroll
        for (int j = 0; j < 8; j++)
            #pragma unroll
            for (int c = 0; c < 4; c++) acc[i][j][c] = 0.f;
        #pragma unroll
        for (int j = 0; j < 4; j++)
            #pragma unroll
            for (int c = 0; c < 4; c++) acc2[i][j][c] = 0.f;
    }

    const float* kbase = k + (size_t)b * L * D + h * DK;
    const float* vbase = v + (size_t)b * L * D + h * DK;
    float* sb = scores + (size_t)bh * L * L;
    int jj = tid >> 1, kc = (tid & 1) * 8;
    int vr = tid >> 1, vc = (tid & 1) * 32;

    auto issueV = [&](int jt) {
        const float* src = vbase + (size_t)(jt * 128 + vr) * D + vc;
        float* dst = u + ATT_VS + (jt & 1) * ATT_VSTRIDE + vr * 72 + vc;
        #pragma unroll
        for (int i = 0; i < 8; i++) cpa16(dst + i * 4, src + i * 4);
        CP_COMMIT();
    };

    {   // prefetch K chunk 0 -> Bs[0]
        const float* src = kbase + (size_t)jj * D + kc;
        float4 ca = *(const float4*)(src), cb = *(const float4*)(src + 4);
        Bs[0][kc+0][jj]=ca.x; Bs[0][kc+1][jj]=ca.y;
        Bs[0][kc+2][jj]=ca.z; Bs[0][kc+3][jj]=ca.w;
        Bs[0][kc+4][jj]=cb.x; Bs[0][kc+5][jj]=cb.y;
        Bs[0][kc+6][jj]=cb.z; Bs[0][kc+7][jj]=cb.w;
    }
    issueV(0);
    __syncthreads();

    for (int jt = 0; jt < 8; jt++) {
        // ---- QK^T over 4 chunks of 16 k each ----
        #pragma unroll
        for (int c = 0; c < 4; c++) {
            int buf = c & 1;
            int nch = jt * 4 + c + 1;
            float4 na, nb;
            if (nch < 32) {
                const float* src = kbase + (size_t)((nch >> 2) * 128 + jj) * D + (nch & 3) * 16 + kc;
                na = *(const float4*)(src); nb = *(const float4*)(src + 4);
            }
            #pragma unroll
            for (int ksl = 0; ksl < 2; ksl++) {
                int kk = c * 16 + ksl * 8;
                unsigned af[2][4], bf[8][2];
                #pragma unroll
                for (int mi = 0; mi < 2; mi++) {
                    int m = wm + mi * 16 + grp;
                    af[mi][0] = __float_as_uint(Qs[m * 68 + kk + tg]);
                    af[mi][1] = __float_as_uint(Qs[(m + 8) * 68 + kk + tg]);
                    af[mi][2] = __float_as_uint(Qs[m * 68 + kk + tg + 4]);
                    af[mi][3] = __float_as_uint(Qs[(m + 8) * 68 + kk + tg + 4]);
                }
                #pragma unroll
                for (int ni = 0; ni < 8; ni++) {
                    int n = wn + ni * 8 + grp;
                    bf[ni][0] = __float_as_uint(Bs[buf][ksl*8 + tg][n]);
                    bf[ni][1] = __float_as_uint(Bs[buf][ksl*8 + tg + 4][n]);
                }
                #pragma unroll
                for (int mi = 0; mi < 2; mi++)
                    #pragma unroll
                    for (int ni = 0; ni < 8; ni++)
                        mma8(acc[mi][ni], af[mi], bf[ni]);
            }
            if (c == 3) {   // epilogue: s -> scores(global) + p -> Ps(smem)
                #pragma unroll
                for (int mi = 0; mi < 2; mi++)
                    #pragma unroll
                    for (int ni = 0; ni < 8; ni++) {
                        int rl = wm + mi * 16 + grp;
                        int cl = wn + ni * 8 + tg * 2;
                        int gj = jt * 128 + cl;
                        #pragma unroll
                        for (int rr = 0; rr < 2; rr++) {
                            int row = i0 + rl + rr * 8;
                            float s0 = acc[mi][ni][rr*2 + 0] * SCALE;
                            float s1 = acc[mi][ni][rr*2 + 1] * SCALE;
                            float2* p = (float2*)(sb + (size_t)row * L + gj);
                            if (add_prev) { float2 pv = *p; s0 += pv.x; s1 += pv.y; }
                            int d0 = row - gj;     d0 = d0 < 0 ? -d0 : d0;
                            int d1 = row - gj - 1; d1 = d1 < 0 ? -d1 : d1;
                            if (d0 < HWIN) s0 = NEG;
                            if (d1 < HWIN) s1 = NEG;
                            *p = make_float2(s0, s1);
                            float p0 = __expf(s0), p1 = __expf(s1);
                            sum_acc[mi*2 + rr] += p0 + p1;
                            float2* pp = (float2*)&Ps[(rl + rr*8) * 132 + cl];
                            *pp = make_float2(p0, p1);
                            acc[mi][ni][rr*2 + 0] = 0.f;
                            acc[mi][ni][rr*2 + 1] = 0.f;
                        }
                    }
            }
            if (nch < 32) {
                int nb2 = buf ^ 1;
                Bs[nb2][kc+0][jj]=na.x; Bs[nb2][kc+1][jj]=na.y;
                Bs[nb2][kc+2][jj]=na.z; Bs[nb2][kc+3][jj]=na.w;
                Bs[nb2][kc+4][jj]=nb.x; Bs[nb2][kc+5][jj]=nb.y;
                Bs[nb2][kc+6][jj]=nb.z; Bs[nb2][kc+7][jj]=nb.w;
            }
            __syncthreads();
        }

        // ---- PV for this j-tile: acc2 += P(128x128) @ V(128x64) ----
        if (jt + 1 < 8) {
            issueV(jt + 1);      // into other buffer; overlaps PV + next QK
            CP_WAIT1();          // V(jt) complete (only V(jt+1) still pending)
        } else {
            CP_WAIT0();
        }
        __syncthreads();         // everyone's V(jt) copies visible
        const float* Vs = u + ATT_VS + (jt & 1) * ATT_VSTRIDE;
        #pragma unroll
        for (int ksl = 0; ksl < 16; ksl++) {
            unsigned a2[2][4], b2[4][2];
            #pragma unroll
            for (int mi = 0; mi < 2; mi++) {
                int m = wm + mi * 16 + grp;
                a2[mi][0] = __float_as_uint(Ps[m * 132 + ksl*8 + tg]);
                a2[mi][1] = __float_as_uint(Ps[(m + 8) * 132 + ksl*8 + tg]);
                a2[mi][2] = __float_as_uint(Ps[m * 132 + ksl*8 + tg + 4]);
                a2[mi][3] = __float_as_uint(Ps[(m + 8) * 132 + ksl*8 + tg + 4]);
            }
            #pragma unroll
            for (int ni = 0; ni < 4; ni++) {
                int n = wn2 + ni * 8 + grp;
                b2[ni][0] = __float_as_uint(Vs[(ksl*8 + tg) * 72 + n]);
                b2[ni][1] = __float_as_uint(Vs[(ksl*8 + tg + 4) * 72 + n]);
            }
            #pragma unroll
            for (int mi = 0; mi < 2; mi++)
                #pragma unroll
                for (int ni = 0; ni < 4; ni++)
                    mma8(acc2[mi][ni], a2[mi], b2[ni]);
        }
        // no post-PV barrier: next writes hit Bs (chunk-loop synced) and the
        // OTHER V buffer; Ps rewritten only after 4 more chunk barriers.
    }

    // ---- row-sum reduction ----
    #pragma unroll
    for (int mi = 0; mi < 2; mi++)
        #pragma unroll
        for (int rr = 0; rr < 2; rr++) {
            float s = sum_acc[mi*2 + rr];
            s += __shfl_xor_sync(0xffffffffu, s, 1);
            s += __shfl_xor_sync(0xffffffffu, s, 2);
            if (tg == 0) m_part[w & 1][wm + mi*16 + grp + rr*8] = s;
        }
    __syncthreads();
    if (tid < 128) inv_row[tid] = 1.0f / (m_part[0][tid] + m_part[1][tid]);
    __syncthreads();

    float* ob = ao + (size_t)b * L * D + h * DK;
    #pragma unroll
    for (int mi = 0; mi < 2; mi++)
        #pragma unroll
        for (int ni = 0; ni < 4; ni++) {
            int rl = wm + mi * 16 + grp;
            int col = wn2 + ni * 8 + tg * 2;
            float iv0 = inv_row[rl], iv1 = inv_row[rl + 8];
            float2* p0 = (float2*)(ob + (size_t)(i0 + rl) * D + col);
            float2* p1 = (float2*)(ob + (size_t)(i0 + rl + 8) * D + col);
            *p0 = make_float2(acc2[mi][ni][0] * iv0, acc2[mi][ni][1] * iv0);
            *p1 = make_float2(acc2[mi][ni][2] * iv1, acc2[mi][ni][3] * iv1);
        }
}

// ============================================================
// out = LayerNorm(x + r) * gamma + beta. One block (128 thr) per row of 512.
// ============================================================
__global__ void addln_kernel(const float* __restrict__ x, const float* __restrict__ r,
                             const float* __restrict__ gam, const float* __restrict__ bet,
                             float* __restrict__ out) {
    int row = blockIdx.x;
    int tid = threadIdx.x;
    const float4* xp = (const float4*)(x + (size_t)row * D);
    const float4* rp = (const float4*)(r + (size_t)row * D);
    float4 a = xp[tid], b4 = rp[tid];
    float e0 = a.x + b4.x, e1 = a.y + b4.y, e2 = a.z + b4.z, e3 = a.w + b4.w;
    float s = e0 + e1 + e2 + e3;
    float qq = e0*e0 + e1*e1 + e2*e2 + e3*e3;
    __shared__ float rs[4], rq[4];
    #pragma unroll
    for (int off = 16; off; off >>= 1) {
        s  += __shfl_xor_sync(0xffffffffu, s, off);
        qq += __shfl_xor_sync(0xffffffffu, qq, off);
    }
    if ((tid & 31) == 0) { rs[tid >> 5] = s; rq[tid >> 5] = qq; }
    __syncthreads();
    s  = rs[0] + rs[1] + rs[2] + rs[3];
    qq = rq[0] + rq[1] + rq[2] + rq[3];
    float mean = s * (1.0f / D);
    float var  = qq * (1.0f / D) - mean * mean;
    float inv  = rsqrtf(var + EPS);
    float4 g4 = ((const float4*)gam)[tid];
    float4 bb = ((const float4*)bet)[tid];
    float4 ov;
    ov.x = (e0 - mean) * inv * g4.x + bb.x;
    ov.y = (e1 - mean) * inv * g4.y + bb.y;
    ov.z = (e2 - mean) * inv * g4.z + bb.z;
    ov.w = (e3 - mean) * inv * g4.w + bb.w;
    ((float4*)(out + (size_t)row * D))[tid] = ov;
}

// ============================================================
extern "C" void kernel_launch(void* const* d_in, const int* in_sizes, int n_in,
                              void* d_out, int out_size) {
    const float* src = (const float*)d_in[0];
    const float* Wq = (const float*)d_in[1];  const float* bq = (const float*)d_in[2];
    const float* Wk = (const float*)d_in[3];  const float* bk = (const float*)d_in[4];
    const float* Wv = (const float*)d_in[5];  const float* bv = (const float*)d_in[6];
    const float* Wo = (const float*)d_in[7];  const float* bo = (const float*)d_in[8];
    const float* W1 = (const float*)d_in[9];  const float* b1 = (const float*)d_in[10];
    const float* W2 = (const float*)d_in[11]; const float* b2 = (const float*)d_in[12];
    const float* ln1g = (const float*)d_in[13]; const float* ln1b = (const float*)d_in[14];
    const float* ln2g = (const float*)d_in[15]; const float* ln2b = (const float*)d_in[16];

    float *q, *k, *v, *x, *tmp, *ao, *ff, *sc;
    cudaGetSymbolAddress((void**)&q,  g_q);
    cudaGetSymbolAddress((void**)&k,  g_k);
    cudaGetSymbolAddress((void**)&v,  g_v);
    cudaGetSymbolAddress((void**)&x,  g_x);
    cudaGetSymbolAddress((void**)&tmp, g_tmp);
    cudaGetSymbolAddress((void**)&ao, g_ao);
    cudaGetSymbolAddress((void**)&ff, g_ff);
    cudaGetSymbolAddress((void**)&sc, g_scores);

    cudaFuncSetAttribute(gemm_tf32<0>, cudaFuncAttributeMaxDynamicSharedMemorySize, GEMM_SMEM);
    cudaFuncSetAttribute(gemm_tf32<1>, cudaFuncAttributeMaxDynamicSharedMemorySize, GEMM_SMEM);
    cudaFuncSetAttribute(qkv_gemm,     cudaFuncAttributeMaxDynamicSharedMemorySize, GEMM_SMEM);
    cudaFuncSetAttribute(attn_fused,   cudaFuncAttributeMaxDynamicSharedMemorySize, ATT_SMEM);

    dim3 gD(D/128, ROWS/128);     // 4 x 32
    dim3 gDF(DF/128, ROWS/128);   // 16 x 32
    dim3 gQKV(12, ROWS/128);      // 12 x 32
    dim3 gA(L/128, BH);           // 8 x 32

    const float* xin = src;
    for (int l = 0; l < NL; l++) {
        qkv_gemm<<<gQKV, 256, GEMM_SMEM>>>(xin,
            Wq + (size_t)l*D*D, bq + (size_t)l*D,
            Wk + (size_t)l*D*D, bk + (size_t)l*D,
            Wv + (size_t)l*D*D, bv + (size_t)l*D, q, k, v);
        attn_fused<<<gA, 256, ATT_SMEM>>>(q, k, v, sc, ao, l > 0 ? 1 : 0);
        gemm_tf32<0><<<gD, 256, GEMM_SMEM>>>(ao, Wo + (size_t)l*D*D, bo + (size_t)l*D, tmp, D, D);
        addln_kernel<<<ROWS, 128>>>(xin, tmp, ln1g + (size_t)l*D, ln1b + (size_t)l*D, x);
        gemm_tf32<1><<<gDF, 256, GEMM_SMEM>>>(x, W1 + (size_t)l*D*DF, b1 + (size_t)l*DF, ff, DF, D);
        gemm_tf32<0><<<gD, 256, GEMM_SMEM>>>(ff, W2 + (size_t)l*DF*D, b2 + (size_t)l*D, tmp, D, DF);
        float* lnout = (l == NL-1) ? (float*)d_out : x;
        addln_kernel<<<ROWS, 128>>>(x, tmp, ln2g + (size_t)l*D, ln2b + (size_t)l*D, lnout);
        xin = x;
    }
}

// round 15
// speedup vs baseline: 1.2074x; 1.0178x over previous
#include <cuda_runtime.h>
#include <math.h>

#define B 4
#define L 1024
#define D 512
#define H 8
#define DK 64
#define DF 2048
#define NL 2
#define HWIN 6
#define SCALE 0.125f
#define NEG -1e9f
#define EPS 1e-5f
#define ROWS (B*L)
#define BH (B*H)

// ---- scratch (device globals; no allocations allowed) ----
__device__ float g_q[B*L*D];
__device__ float g_k[B*L*D];
__device__ float g_v[B*L*D];
__device__ float g_x[B*L*D];
__device__ float g_tmp[B*L*D];
__device__ float g_ao[B*L*D];
__device__ float g_ff[B*L*DF];
__device__ float g_zero[D];                  // zero-initialized (zero bias for split z=1)
__device__ float g_scores[(size_t)BH*L*L];   // masked pre-softmax scores (carried across layers)

// ============================================================
// helpers: raw-bit tf32 (HW truncates), mma, cp.async
// ============================================================
__device__ __forceinline__ void mma8(float* d, const unsigned* a, const unsigned* b) {
    asm volatile("mma.sync.aligned.m16n8k8.row.col.f32.tf32.tf32.f32 "
                 "{%0,%1,%2,%3}, {%4,%5,%6,%7}, {%8,%9}, {%0,%1,%2,%3};\n"
                 : "+f"(d[0]), "+f"(d[1]), "+f"(d[2]), "+f"(d[3])
                 : "r"(a[0]), "r"(a[1]), "r"(a[2]), "r"(a[3]),
                   "r"(b[0]), "r"(b[1]));
}
__device__ __forceinline__ void cpa16(float* s, const float* g) {
    unsigned a = (unsigned)__cvta_generic_to_shared(s);
    asm volatile("cp.async.cg.shared.global [%0], [%1], 16;\n" :: "r"(a), "l"(g));
}
#define CP_COMMIT() asm volatile("cp.async.commit_group;\n" ::: "memory")
#define CP_WAIT0()  asm volatile("cp.async.wait_group 0;\n" ::: "memory")
#define CP_WAIT1()  asm volatile("cp.async.wait_group 1;\n" ::: "memory")

// dynamic smem layout for GEMM: 3 stages (R7/R11 config)
#define AST 2560
#define BST 2176
#define GEMM_SMEM (3*(AST+BST)*4)   // 56832 bytes

// ============================================================
// GEMM body (R13/R14 winner): 128x128 tile, BK=16, 3-stage cp.async,
// single barrier per K-tile.
// ============================================================
template<int GELU>
__device__ __forceinline__ void gemm_body(const float* __restrict__ A,
                                          const float* __restrict__ W,
                                          const float* __restrict__ bias,
                                          float* __restrict__ C,
                                          int N, int K, int bm, int bn,
                                          float* smA, float* smB) {
    int tid = threadIdx.x;
    int lane = tid & 31, w = tid >> 5;
    int grp = lane >> 2, tg = lane & 3;
    int wm = (w >> 1) * 32, wn = (w & 1) * 64;
    int ar = tid >> 1, ac = (tid & 1) * 8;
    int br = tid >> 4, bc = (tid & 15) * 8;

    float acc[2][8][4];
    #pragma unroll
    for (int i = 0; i < 2; i++)
        #pragma unroll
        for (int j = 0; j < 8; j++)
            #pragma unroll
            for (int c = 0; c < 4; c++) acc[i][j][c] = 0.f;

    const float* Ap = A + (size_t)(bm + ar) * K + ac;
    const float* Wp = W + (size_t)br * N + bn + bc;
    // NOTE: K here is the (possibly reduced) contraction length; caller
    // pre-offsets A/W for split-K. Stride of A rows passed via Kst.
    int T = K >> 4;

    auto issue = [&](int t) {
        int s = t % 3;
        const float* a = Ap + (t << 4);
        cpa16(&smA[s*AST + ar*20 + ac],     a);
        cpa16(&smA[s*AST + ar*20 + ac + 4], a + 4);
        const float* bsrc = Wp + (size_t)(t << 4) * N;
        cpa16(&smB[s*BST + br*136 + bc],     bsrc);
        cpa16(&smB[s*BST + br*136 + bc + 4], bsrc + 4);
    };

    if (0 < T) issue(0);
    CP_COMMIT();
    if (1 < T) issue(1);
    CP_COMMIT();

    for (int t = 0; t < T; t++) {
        CP_WAIT1();
        __syncthreads();
        if (t + 2 < T) issue(t + 2);
        CP_COMMIT();
        const float* As = &smA[(t % 3) * AST];
        const float* Bs = &smB[(t % 3) * BST];
        #pragma unroll
        for (int ks = 0; ks < 16; ks += 8) {
            unsigned af[2][4], bf[8][2];
            #pragma unroll
            for (int mi = 0; mi < 2; mi++) {
                int m = wm + mi * 16 + grp;
                af[mi][0] = __float_as_uint(As[m*20 + ks + tg]);
                af[mi][1] = __float_as_uint(As[(m+8)*20 + ks + tg]);
                af[mi][2] = __float_as_uint(As[m*20 + ks + tg + 4]);
                af[mi][3] = __float_as_uint(As[(m+8)*20 + ks + tg + 4]);
            }
            #pragma unroll
            for (int ni = 0; ni < 8; ni++) {
                int n = wn + ni * 8 + grp;
                bf[ni][0] = __float_as_uint(Bs[(ks+tg)*136 + n]);
                bf[ni][1] = __float_as_uint(Bs[(ks+tg+4)*136 + n]);
            }
            #pragma unroll
            for (int mi = 0; mi < 2; mi++)
                #pragma unroll
                for (int ni = 0; ni < 8; ni++)
                    mma8(acc[mi][ni], af[mi], bf[ni]);
        }
    }

    #pragma unroll
    for (int mi = 0; mi < 2; mi++)
        #pragma unroll
        for (int ni = 0; ni < 8; ni++) {
            int row = bm + wm + mi * 16 + grp;
            int col = bn + wn + ni * 8 + tg * 2;
            float bs0 = bias[col], bs1 = bias[col + 1];
            float v0 = acc[mi][ni][0] + bs0, v1 = acc[mi][ni][1] + bs1;
            float v2 = acc[mi][ni][2] + bs0, v3 = acc[mi][ni][3] + bs1;
            if (GELU) {
                v0 = 0.5f * v0 * (1.0f + erff(v0 * 0.70710678118654752f));
                v1 = 0.5f * v1 * (1.0f + erff(v1 * 0.70710678118654752f));
                v2 = 0.5f * v2 * (1.0f + erff(v2 * 0.70710678118654752f));
                v3 = 0.5f * v3 * (1.0f + erff(v3 * 0.70710678118654752f));
            }
            float2* p0 = (float2*)(C + (size_t)row * N + col);
            float2* p1 = (float2*)(C + (size_t)(row + 8) * N + col);
            *p0 = make_float2(v0, v1);
            *p1 = make_float2(v2, v3);
        }
}

// A-row-stride-aware variant wrapper is not needed: for split-K we offset A by
// the k-start and pass the FULL row stride via Kst below.
template<int GELU>
__device__ __forceinline__ void gemm_body_stride(const float* __restrict__ A,
                                                 const float* __restrict__ W,
                                                 const float* __restrict__ bias,
                                                 float* __restrict__ C,
                                                 int N, int K, int Kst, int bm, int bn,
                                                 float* smA, float* smB) {
    int tid = threadIdx.x;
    int lane = tid & 31, w = tid >> 5;
    int grp = lane >> 2, tg = lane & 3;
    int wm = (w >> 1) * 32, wn = (w & 1) * 64;
    int ar = tid >> 1, ac = (tid & 1) * 8;
    int br = tid >> 4, bc = (tid & 15) * 8;

    float acc[2][8][4];
    #pragma unroll
    for (int i = 0; i < 2; i++)
        #pragma unroll
        for (int j = 0; j < 8; j++)
            #pragma unroll
            for (int c = 0; c < 4; c++) acc[i][j][c] = 0.f;

    const float* Ap = A + (size_t)(bm + ar) * Kst + ac;
    const float* Wp = W + (size_t)br * N + bn + bc;
    int T = K >> 4;

    auto issue = [&](int t) {
        int s = t % 3;
        const float* a = Ap + (t << 4);
        cpa16(&smA[s*AST + ar*20 + ac],     a);
        cpa16(&smA[s*AST + ar*20 + ac + 4], a + 4);
        const float* bsrc = Wp + (size_t)(t << 4) * N;
        cpa16(&smB[s*BST + br*136 + bc],     bsrc);
        cpa16(&smB[s*BST + br*136 + bc + 4], bsrc + 4);
    };

    if (0 < T) issue(0);
    CP_COMMIT();
    if (1 < T) issue(1);
    CP_COMMIT();

    for (int t = 0; t < T; t++) {
        CP_WAIT1();
        __syncthreads();
        if (t + 2 < T) issue(t + 2);
        CP_COMMIT();
        const float* As = &smA[(t % 3) * AST];
        const float* Bs = &smB[(t % 3) * BST];
        #pragma unroll
        for (int ks = 0; ks < 16; ks += 8) {
            unsigned af[2][4], bf[8][2];
            #pragma unroll
            for (int mi = 0; mi < 2; mi++) {
                int m = wm + mi * 16 + grp;
                af[mi][0] = __float_as_uint(As[m*20 + ks + tg]);
                af[mi][1] = __float_as_uint(As[(m+8)*20 + ks + tg]);
                af[mi][2] = __float_as_uint(As[m*20 + ks + tg + 4]);
                af[mi][3] = __float_as_uint(As[(m+8)*20 + ks + tg + 4]);
            }
            #pragma unroll
            for (int ni = 0; ni < 8; ni++) {
                int n = wn + ni * 8 + grp;
                bf[ni][0] = __float_as_uint(Bs[(ks+tg)*136 + n]);
                bf[ni][1] = __float_as_uint(Bs[(ks+tg+4)*136 + n]);
            }
            #pragma unroll
            for (int mi = 0; mi < 2; mi++)
                #pragma unroll
                for (int ni = 0; ni < 8; ni++)
                    mma8(acc[mi][ni], af[mi], bf[ni]);
        }
    }

    #pragma unroll
    for (int mi = 0; mi < 2; mi++)
        #pragma unroll
        for (int ni = 0; ni < 8; ni++) {
            int row = bm + wm + mi * 16 + grp;
            int col = bn + wn + ni * 8 + tg * 2;
            float bs0 = bias[col], bs1 = bias[col + 1];
            float v0 = acc[mi][ni][0] + bs0, v1 = acc[mi][ni][1] + bs1;
            float v2 = acc[mi][ni][2] + bs0, v3 = acc[mi][ni][3] + bs1;
            float2* p0 = (float2*)(C + (size_t)row * N + col);
            float2* p1 = (float2*)(C + (size_t)(row + 8) * N + col);
            *p0 = make_float2(v0, v1);
            *p1 = make_float2(v2, v3);
        }
}

template<int GELU>
__global__ __launch_bounds__(256, 2) void gemm_tf32(const float* __restrict__ A,
                                                    const float* __restrict__ W,
                                                    const float* __restrict__ bias,
                                                    float* __restrict__ C,
                                                    int N, int K) {
    extern __shared__ float dyn[];
    gemm_body<GELU>(A, W, bias, C, N, K, blockIdx.y * 128, blockIdx.x * 128,
                    dyn, dyn + 3*AST);
}

// split-K GEMM: gridDim.z=2; z picks k-half. z=0 adds bias -> C0; z=1 adds
// zero-bias -> C1. No GELU (used for Wo / FF2 only).
__global__ __launch_bounds__(256, 2) void gemm_split(const float* __restrict__ A,
                                                     const float* __restrict__ W,
                                                     const float* __restrict__ bias,
                                                     const float* __restrict__ zbias,
                                                     float* __restrict__ C0,
                                                     float* __restrict__ C1,
                                                     int N, int Khalf, int Kst) {
    extern __shared__ float dyn[];
    int z = blockIdx.z;
    gemm_body_stride<0>(A + (size_t)z * Khalf,
                        W + (size_t)z * Khalf * N,
                        z ? zbias : bias,
                        z ? C1 : C0,
                        N, Khalf, Kst, blockIdx.y * 128, blockIdx.x * 128,
                        dyn, dyn + 3*AST);
}

// fused QKV: blockIdx.x in [0,12): sel = bx>>2 picks {q,k,v}, (bx&3) n-tile.
__global__ __launch_bounds__(256, 2) void qkv_gemm(const float* __restrict__ A,
        const float* __restrict__ Wq, const float* __restrict__ bq,
        const float* __restrict__ Wk, const float* __restrict__ bk,
        const float* __restrict__ Wv, const float* __restrict__ bv,
        float* __restrict__ q, float* __restrict__ k, float* __restrict__ v) {
    extern __shared__ float dyn[];
    int sel = blockIdx.x >> 2;
    const float* W = sel == 0 ? Wq : (sel == 1 ? Wk : Wv);
    const float* bias = sel == 0 ? bq : (sel == 1 ? bk : bv);
    float* C = sel == 0 ? q : (sel == 1 ? k : v);
    gemm_body<0>(A, W, bias, C, D, D, blockIdx.y * 128, (blockIdx.x & 3) * 128,
                 dyn, dyn + 3*AST);
}

// ============================================================
// Single-pass fused attention (unchanged from R14 winner).
// ============================================================
#define ATT_QS 0
#define ATT_BS 8704
#define ATT_PS 13056
#define ATT_VS 29952
#define ATT_VSTRIDE 9216
#define ATT_SMEM (48384*4)   // 193536 bytes

__global__ __launch_bounds__(256) void attn_fused(const float* __restrict__ q,
                                                  const float* __restrict__ k,
                                                  const float* __restrict__ v,
                                                  float* __restrict__ scores,
                                                  float* __restrict__ ao,
                                                  int add_prev) {
    __shared__ float m_part[2][128];
    __shared__ float inv_row[128];
    extern __shared__ float u[];
    float* Qs = u + ATT_QS;
    float (*Bs)[16][136] = (float (*)[16][136])(u + ATT_BS);
    float* Ps = u + ATT_PS;

    int bh = blockIdx.y;
    int b = bh >> 3, h = bh & 7;
    int i0 = blockIdx.x * 128;
    int tid = threadIdx.x, lane = tid & 31, w = tid >> 5;
    int grp = lane >> 2, tg = lane & 3;
    int wm = (w >> 1) * 32, wn = (w & 1) * 64, wn2 = (w & 1) * 32;

    {
        const float4* qsrc = (const float4*)(q + ((size_t)b * L + i0) * D + h * DK);
        #pragma unroll
        for (int it = 0; it < 8; it++) {
            int idx = tid + it * 256;
            int row = idx >> 4, c4 = idx & 15;
            float4 t = qsrc[(size_t)row * (D / 4) + c4];
            float* dst = &Qs[row * 68 + c4 * 4];
            dst[0] = t.x; dst[1] = t.y; dst[2] = t.z; dst[3] = t.w;
        }
    }

    float acc[2][8][4];
    float acc2[2][4][4];
    float sum_acc[4] = {0.f, 0.f, 0.f, 0.f};
    #pragma unroll
    for (int i = 0; i < 2; i++) {
        #pragma unroll
        for (int j = 0; j < 8; j++)
            #pragma unroll
            for (int c = 0; c < 4; c++) acc[i][j][c] = 0.f;
        #pragma unroll
        for (int j = 0; j < 4; j++)
            #pragma unroll
            for (int c = 0; c < 4; c++) acc2[i][j][c] = 0.f;
    }

    const float* kbase = k + (size_t)b * L * D + h * DK;
    const float* vbase = v + (size_t)b * L * D + h * DK;
    float* sb = scores + (size_t)bh * L * L;
    int jj = tid >> 1, kc = (tid & 1) * 8;
    int vr = tid >> 1, vc = (tid & 1) * 32;

    auto issueV = [&](int jt) {
        const float* src = vbase + (size_t)(jt * 128 + vr) * D + vc;
        float* dst = u + ATT_VS + (jt & 1) * ATT_VSTRIDE + vr * 72 + vc;
        #pragma unroll
        for (int i = 0; i < 8; i++) cpa16(dst + i * 4, src + i * 4);
        CP_COMMIT();
    };

    {
        const float* src = kbase + (size_t)jj * D + kc;
        float4 ca = *(const float4*)(src), cb = *(const float4*)(src + 4);
        Bs[0][kc+0][jj]=ca.x; Bs[0][kc+1][jj]=ca.y;
        Bs[0][kc+2][jj]=ca.z; Bs[0][kc+3][jj]=ca.w;
        Bs[0][kc+4][jj]=cb.x; Bs[0][kc+5][jj]=cb.y;
        Bs[0][kc+6][jj]=cb.z; Bs[0][kc+7][jj]=cb.w;
    }
    issueV(0);
    __syncthreads();

    for (int jt = 0; jt < 8; jt++) {
        #pragma unroll
        for (int c = 0; c < 4; c++) {
            int buf = c & 1;
            int nch = jt * 4 + c + 1;
            float4 na, nb;
            if (nch < 32) {
                const float* src = kbase + (size_t)((nch >> 2) * 128 + jj) * D + (nch & 3) * 16 + kc;
                na = *(const float4*)(src); nb = *(const float4*)(src + 4);
            }
            #pragma unroll
            for (int ksl = 0; ksl < 2; ksl++) {
                int kk = c * 16 + ksl * 8;
                unsigned af[2][4], bf[8][2];
                #pragma unroll
                for (int mi = 0; mi < 2; mi++) {
                    int m = wm + mi * 16 + grp;
                    af[mi][0] = __float_as_uint(Qs[m * 68 + kk + tg]);
                    af[mi][1] = __float_as_uint(Qs[(m + 8) * 68 + kk + tg]);
                    af[mi][2] = __float_as_uint(Qs[m * 68 + kk + tg + 4]);
                    af[mi][3] = __float_as_uint(Qs[(m + 8) * 68 + kk + tg + 4]);
                }
                #pragma unroll
                for (int ni = 0; ni < 8; ni++) {
                    int n = wn + ni * 8 + grp;
                    bf[ni][0] = __float_as_uint(Bs[buf][ksl*8 + tg][n]);
                    bf[ni][1] = __float_as_uint(Bs[buf][ksl*8 + tg + 4][n]);
                }
                #pragma unroll
                for (int mi = 0; mi < 2; mi++)
                    #pragma unroll
                    for (int ni = 0; ni < 8; ni++)
                        mma8(acc[mi][ni], af[c >= 0 ? mi : mi][0 ? 0 : 0] == 0 ? af[mi] : af[mi], bf[ni]);
            }
            if (c == 3) {
                #pragma unroll
                for (int mi = 0; mi < 2; mi++)
                    #pragma unroll
                    for (int ni = 0; ni < 8; ni++) {
                        int rl = wm + mi * 16 + grp;
                        int cl = wn + ni * 8 + tg * 2;
                        int gj = jt * 128 + cl;
                        #pragma unroll
                        for (int rr = 0; rr < 2; rr++) {
                            int row = i0 + rl + rr * 8;
                            float s0 = acc[mi][ni][rr*2 + 0] * SCALE;
                            float s1 = acc[mi][ni][rr*2 + 1] * SCALE;
                            float2* p = (float2*)(sb + (size_t)row * L + gj);
                            if (add_prev) { float2 pv = *p; s0 += pv.x; s1 += pv.y; }
                            int d0 = row - gj;     d0 = d0 < 0 ? -d0 : d0;
                            int d1 = row - gj - 1; d1 = d1 < 0 ? -d1 : d1;
                            if (d0 < HWIN) s0 = NEG;
                            if (d1 < HWIN) s1 = NEG;
                            *p = make_float2(s0, s1);
                            float p0 = __expf(s0), p1 = __expf(s1);
                            sum_acc[mi*2 + rr] += p0 + p1;
                            float2* pp = (float2*)&Ps[(rl + rr*8) * 132 + cl];
                            *pp = make_float2(p0, p1);
                            acc[mi][ni][rr*2 + 0] = 0.f;
                            acc[mi][ni][rr*2 + 1] = 0.f;
                        }
                    }
            }
            if (nch < 32) {
                int nb2 = buf ^ 1;
                Bs[nb2][kc+0][jj]=na.x; Bs[nb2][kc+1][jj]=na.y;
                Bs[nb2][kc+2][jj]=na.z; Bs[nb2][kc+3][jj]=na.w;
                Bs[nb2][kc+4][jj]=nb.x; Bs[nb2][kc+5][jj]=nb.y;
                Bs[nb2][kc+6][jj]=nb.z; Bs[nb2][kc+7][jj]=nb.w;
            }
            __syncthreads();
        }

        if (jt + 1 < 8) {
            issueV(jt + 1);
            CP_WAIT1();
        } else {
            CP_WAIT0();
        }
        __syncthreads();
        const float* Vs = u + ATT_VS + (jt & 1) * ATT_VSTRIDE;
        #pragma unroll
        for (int ksl = 0; ksl < 16; ksl++) {
            unsigned a2[2][4], b2[4][2];
            #pragma unroll
            for (int mi = 0; mi < 2; mi++) {
                int m = wm + mi * 16 + grp;
                a2[mi][0] = __float_as_uint(Ps[m * 132 + ksl*8 + tg]);
                a2[mi][1] = __float_as_uint(Ps[(m + 8) * 132 + ksl*8 + tg]);
                a2[mi][2] = __float_as_uint(Ps[m * 132 + ksl*8 + tg + 4]);
                a2[mi][3] = __float_as_uint(Ps[(m + 8) * 132 + ksl*8 + tg + 4]);
            }
            #pragma unroll
            for (int ni = 0; ni < 4; ni++) {
                int n = wn2 + ni * 8 + grp;
                b2[ni][0] = __float_as_uint(Vs[(ksl*8 + tg) * 72 + n]);
                b2[ni][1] = __float_as_uint(Vs[(ksl*8 + tg + 4) * 72 + n]);
            }
            #pragma unroll
            for (int mi = 0; mi < 2; mi++)
                #pragma unroll
                for (int ni = 0; ni < 4; ni++)
                    mma8(acc2[mi][ni], a2[mi], b2[ni]);
        }
    }

    #pragma unroll
    for (int mi = 0; mi < 2; mi++)
        #pragma unroll
        for (int rr = 0; rr < 2; rr++) {
            float s = sum_acc[mi*2 + rr];
            s += __shfl_xor_sync(0xffffffffu, s, 1);
            s += __shfl_xor_sync(0xffffffffu, s, 2);
            if (tg == 0) m_part[w & 1][wm + mi*16 + grp + rr*8] = s;
        }
    __syncthreads();
    if (tid < 128) inv_row[tid] = 1.0f / (m_part[0][tid] + m_part[1][tid]);
    __syncthreads();

    float* ob = ao + (size_t)b * L * D + h * DK;
    #pragma unroll
    for (int mi = 0; mi < 2; mi++)
        #pragma unroll
        for (int ni = 0; ni < 4; ni++) {
            int rl = wm + mi * 16 + grp;
            int col = wn2 + ni * 8 + tg * 2;
            float iv0 = inv_row[rl], iv1 = inv_row[rl + 8];
            float2* p0 = (float2*)(ob + (size_t)(i0 + rl) * D + col);
            float2* p1 = (float2*)(ob + (size_t)(i0 + rl + 8) * D + col);
            *p0 = make_float2(acc2[mi][ni][0] * iv0, acc2[mi][ni][1] * iv0);
            *p1 = make_float2(acc2[mi][ni][2] * iv1, acc2[mi][ni][3] * iv1);
        }
}

// ============================================================
// out = LayerNorm(x + r1 + r2) * gamma + beta. 128 thr per row of 512.
// ============================================================
__global__ void addln3_kernel(const float* __restrict__ x, const float* __restrict__ r1,
                              const float* __restrict__ r2,
                              const float* __restrict__ gam, const float* __restrict__ bet,
                              float* __restrict__ out) {
    int row = blockIdx.x;
    int tid = threadIdx.x;
    const float4* xp = (const float4*)(x + (size_t)row * D);
    const float4* r1p = (const float4*)(r1 + (size_t)row * D);
    const float4* r2p = (const float4*)(r2 + (size_t)row * D);
    float4 a = xp[tid], b4 = r1p[tid], c4 = r2p[tid];
    float e0 = a.x + b4.x + c4.x, e1 = a.y + b4.y + c4.y;
    float e2 = a.z + b4.z + c4.z, e3 = a.w + b4.w + c4.w;
    float s = e0 + e1 + e2 + e3;
    float qq = e0*e0 + e1*e1 + e2*e2 + e3*e3;
    __shared__ float rs[4], rq[4];
    #pragma unroll
    for (int off = 16; off; off >>= 1) {
        s  += __shfl_xor_sync(0xffffffffu, s, off);
        qq += __shfl_xor_sync(0xffffffffu, qq, off);
    }
    if ((tid & 31) == 0) { rs[tid >> 5] = s; rq[tid >> 5] = qq; }
    __syncthreads();
    s  = rs[0] + rs[1] + rs[2] + rs[3];
    qq = rq[0] + rq[1] + rq[2] + rq[3];
    float mean = s * (1.0f / D);
    float var  = qq * (1.0f / D) - mean * mean;
    float inv  = rsqrtf(var + EPS);
    float4 g4 = ((const float4*)gam)[tid];
    float4 bb = ((const float4*)bet)[tid];
    float4 ov;
    ov.x = (e0 - mean) * inv * g4.x + bb.x;
    ov.y = (e1 - mean) * inv * g4.y + bb.y;
    ov.z = (e2 - mean) * inv * g4.z + bb.z;
    ov.w = (e3 - mean) * inv * g4.w + bb.w;
    ((float4*)(out + (size_t)row * D))[tid] = ov;
}

// ============================================================
extern "C" void kernel_launch(void* const* d_in, const int* in_sizes, int n_in,
                              void* d_out, int out_size) {
    const float* src = (const float*)d_in[0];
    const float* Wq = (const float*)d_in[1];  const float* bq = (const float*)d_in[2];
    const float* Wk = (const float*)d_in[3];  const float* bk = (const float*)d_in[4];
    const float* Wv = (const float*)d_in[5];  const float* bv = (const float*)d_in[6];
    const float* Wo = (const float*)d_in[7];  const float* bo = (const float*)d_in[8];
    const float* W1 = (const float*)d_in[9];  const float* b1 = (const float*)d_in[10];
    const float* W2 = (const float*)d_in[11]; const float* b2 = (const float*)d_in[12];
    const float* ln1g = (const float*)d_in[13]; const float* ln1b = (const float*)d_in[14];
    const float* ln2g = (const float*)d_in[15]; const float* ln2b = (const float*)d_in[16];

    float *q, *k, *v, *x, *tmp, *ao, *ff, *sc, *zb;
    cudaGetSymbolAddress((void**)&q,  g_q);
    cudaGetSymbolAddress((void**)&k,  g_k);
    cudaGetSymbolAddress((void**)&v,  g_v);
    cudaGetSymbolAddress((void**)&x,  g_x);
    cudaGetSymbolAddress((void**)&tmp, g_tmp);
    cudaGetSymbolAddress((void**)&ao, g_ao);
    cudaGetSymbolAddress((void**)&ff, g_ff);
    cudaGetSymbolAddress((void**)&sc, g_scores);
    cudaGetSymbolAddress((void**)&zb, g_zero);

    cudaFuncSetAttribute(gemm_tf32<0>, cudaFuncAttributeMaxDynamicSharedMemorySize, GEMM_SMEM);
    cudaFuncSetAttribute(gemm_tf32<1>, cudaFuncAttributeMaxDynamicSharedMemorySize, GEMM_SMEM);
    cudaFuncSetAttribute(gemm_split,   cudaFuncAttributeMaxDynamicSharedMemorySize, GEMM_SMEM);
    cudaFuncSetAttribute(qkv_gemm,     cudaFuncAttributeMaxDynamicSharedMemorySize, GEMM_SMEM);
    cudaFuncSetAttribute(attn_fused,   cudaFuncAttributeMaxDynamicSharedMemorySize, ATT_SMEM);

    dim3 gDF(DF/128, ROWS/128);      // 16 x 32 (FF1)
    dim3 gQKV(12, ROWS/128);         // 12 x 32
    dim3 gA(L/128, BH);              // 8 x 32
    dim3 gSplit(D/128, ROWS/128, 2); // 4 x 32 x 2 (Wo, FF2)

    const float* xin = src;
    for (int l = 0; l < NL; l++) {
        qkv_gemm<<<gQKV, 256, GEMM_SMEM>>>(xin,
            Wq + (size_t)l*D*D, bq + (size_t)l*D,
            Wk + (size_t)l*D*D, bk + (size_t)l*D,
            Wv + (size_t)l*D*D, bv + (size_t)l*D, q, k, v);
        attn_fused<<<gA, 256, ATT_SMEM>>>(q, k, v, sc, ao, l > 0 ? 1 : 0);
        // Wo split-K: K=512 -> 2x256, partials in tmp + q (q dead after attn)
        gemm_split<<<gSplit, 256, GEMM_SMEM>>>(ao, Wo + (size_t)l*D*D,
            bo + (size_t)l*D, zb, tmp, q, D, D/2, D);
        addln3_kernel<<<ROWS, 128>>>(xin, tmp, q,
            ln1g + (size_t)l*D, ln1b + (size_t)l*D, x);
        gemm_tf32<1><<<gDF, 256, GEMM_SMEM>>>(x, W1 + (size_t)l*D*DF, b1 + (size_t)l*DF, ff, DF, D);
        // FF2 split-K: K=2048 -> 2x1024, partials in tmp + q
        gemm_split<<<gSplit, 256, GEMM_SMEM>>>(ff, W2 + (size_t)l*DF*D,
            b2 + (size_t)l*D, zb, tmp, q, D, DF/2, DF);
        float* lnout = (l == NL-1) ? (float*)d_out : x;
        addln3_kernel<<<ROWS, 128>>>(x, tmp, q,
            ln2g + (size_t)l*D, ln2b + (size_t)l*D, lnout);
        xin = x;
    }
}